// round 1
// baseline (speedup 1.0000x reference)
#include <cuda_runtime.h>
#include <cuda_bf16.h>

// Problem constants
#define B_   2
#define T_   1024
#define CH_  1024
#define H_   16
#define KC_  64
#define WIN_ 4
#define MROWS (B_ * T_)          // 2048
#define BHT  (B_ * H_ * T_)      // 32768

// ---------------- scratch (static device globals; no allocation) ----------------
__device__ float g_q[B_ * H_ * T_ * KC_];     // [B,H,T,KC], pre-scaled by 1/sqrt(KC)
__device__ float g_k[B_ * H_ * T_ * KC_];
__device__ float g_v[B_ * H_ * T_ * KC_];
__device__ float g_rl[BHT * 9];               // qs . emb_rel_k[u], u=0..8
__device__ float g_scores[B_ * H_ * T_ * T_]; // scores, then softmax in place
__device__ float g_att[MROWS * CH_];          // attention output before Wo

// ---------------- GEMM: C[2048,1024] = scale*(A[2048,1024] @ W[1024,1024] + bias) ---
// mode 0/1/2 : write to g_q/g_k/g_v in [B,H,T,KC] layout
// mode 3     : A := g_att, write row-major to out_direct
#define GTM 128
#define GTN 64
#define GTK 16
__global__ __launch_bounds__(256) void gemm_kernel(
    const float* __restrict__ A, const float* __restrict__ W,
    const float* __restrict__ bias, float scale,
    float* __restrict__ out_direct, int mode)
{
    __shared__ float As[GTK][132];   // [k][m], padded for float4-aligned rows
    __shared__ float Ws[GTK][GTN];   // [k][n]

    const float* Ap = (mode == 3) ? g_att : A;
    float* outp = (mode == 0) ? g_q : (mode == 1) ? g_k : (mode == 2) ? g_v : out_direct;

    int tid = threadIdx.x;
    int bx = blockIdx.x;            // N tile (16)
    int by = blockIdx.y;            // M tile (16)
    int tg = tid >> 4;              // row group 0..15 (8 rows each)
    int tc = tid & 15;              // col group 0..15 (4 cols each)

    float acc[8][4];
#pragma unroll
    for (int r = 0; r < 8; ++r)
#pragma unroll
        for (int j = 0; j < 4; ++j) acc[r][j] = 0.f;

    for (int k0 = 0; k0 < 1024; k0 += GTK) {
        // load A tile: 128 rows x 16 k
#pragma unroll
        for (int u = 0; u < 8; ++u) {
            int lin = tid + u * 256;            // 0..2047
            int m = lin >> 4, kk = lin & 15;
            As[kk][m] = Ap[(by * GTM + m) * 1024 + k0 + kk];
        }
        // load W tile: 16 k x 64 n
#pragma unroll
        for (int u = 0; u < 4; ++u) {
            int lin = tid + u * 256;            // 0..1023
            int kk = lin >> 6, n = lin & 63;
            Ws[kk][n] = W[(k0 + kk) * 1024 + bx * GTN + n];
        }
        __syncthreads();
#pragma unroll
        for (int kk = 0; kk < GTK; ++kk) {
            float4 a0 = *(const float4*)&As[kk][tg * 8];
            float4 a1 = *(const float4*)&As[kk][tg * 8 + 4];
            float4 w0 = *(const float4*)&Ws[kk][tc * 4];
            float av[8] = {a0.x, a0.y, a0.z, a0.w, a1.x, a1.y, a1.z, a1.w};
            float wv[4] = {w0.x, w0.y, w0.z, w0.w};
#pragma unroll
            for (int r = 0; r < 8; ++r)
#pragma unroll
                for (int j = 0; j < 4; ++j)
                    acc[r][j] += av[r] * wv[j];
        }
        __syncthreads();
    }

#pragma unroll
    for (int r = 0; r < 8; ++r) {
        int m = by * GTM + tg * 8 + r;
#pragma unroll
        for (int j = 0; j < 4; ++j) {
            int n = bx * GTN + tc * 4 + j;
            float v = scale * (acc[r][j] + bias[n]);
            if (mode < 3) {
                // [B,H,T,KC]: ((b*H+h)*T + t)*KC + d
                int idx = (((m >> 10) * H_ + (n >> 6)) << 16) | ((m & 1023) << 6) | (n & 63);
                outp[idx] = v;
            } else {
                outp[m * 1024 + n] = v;
            }
        }
    }
}

// ---------------- rel-key logits: g_rl[row][u] = g_q[row,:] . erk[u,:] -------------
__global__ __launch_bounds__(256) void rl_kernel(const float* __restrict__ erk)
{
    __shared__ float e[9 * 64];
    int tid = threadIdx.x;
    for (int u = tid; u < 576; u += 256) e[u] = erk[u];
    __syncthreads();
    int warp = tid >> 5, lane = tid & 31;
    int row = blockIdx.x * 8 + warp;         // 0..32767
    const float* q = g_q + row * 64;
    float q0 = q[lane], q1 = q[lane + 32];
#pragma unroll
    for (int u = 0; u < 9; ++u) {
        float s = q0 * e[u * 64 + lane] + q1 * e[u * 64 + lane + 32];
#pragma unroll
        for (int off = 16; off > 0; off >>= 1)
            s += __shfl_xor_sync(0xffffffffu, s, off);
        if (lane == 0) g_rl[row * 9 + u] = s;
    }
}

// ---------------- scores: S = Qs @ K^T + band(rel_k) , mask --------------------
__global__ __launch_bounds__(256) void scores_kernel(const int* __restrict__ mask)
{
    __shared__ float Qs[64][68];    // [d][i]
    __shared__ float Ks[64][68];    // [d][j]
    int bh = blockIdx.z;
    int i0 = blockIdx.y * 64, j0 = blockIdx.x * 64;
    int tid = threadIdx.x;
    const float* qp = g_q + (bh * 1024 + i0) * 64;
    const float* kp = g_k + (bh * 1024 + j0) * 64;
#pragma unroll
    for (int u = 0; u < 16; ++u) {
        int lin = tid + u * 256;       // 0..4095
        int r = lin >> 6, dd = lin & 63;
        Qs[dd][r] = qp[r * 64 + dd];
        Ks[dd][r] = kp[r * 64 + dd];
    }
    __syncthreads();
    int ti = tid >> 4, tj = tid & 15;
    float acc[4][4];
#pragma unroll
    for (int a = 0; a < 4; ++a)
#pragma unroll
        for (int b = 0; b < 4; ++b) acc[a][b] = 0.f;
#pragma unroll 8
    for (int kk = 0; kk < 64; ++kk) {
        float4 a4 = *(const float4*)&Qs[kk][ti * 4];
        float4 b4 = *(const float4*)&Ks[kk][tj * 4];
        float av[4] = {a4.x, a4.y, a4.z, a4.w};
        float bv[4] = {b4.x, b4.y, b4.z, b4.w};
#pragma unroll
        for (int a = 0; a < 4; ++a)
#pragma unroll
            for (int b = 0; b < 4; ++b)
                acc[a][b] += av[a] * bv[b];
    }
    int bb = bh >> 4;
#pragma unroll
    for (int a = 0; a < 4; ++a) {
        int i = i0 + ti * 4 + a;
#pragma unroll
        for (int b = 0; b < 4; ++b) {
            int j = j0 + tj * 4 + b;
            float s = acc[a][b];
            int d = j - i;
            if (d >= -WIN_ && d <= WIN_)
                s += g_rl[(bh * 1024 + i) * 9 + d + WIN_];
            if (mask[(bb * 1024 + i) * 1024 + j] == 0) s = 1e-4f;
            g_scores[((bh * 1024 + i) << 10) + j] = s;
        }
    }
}

// ---------------- softmax in place over rows of g_scores ----------------------
__global__ __launch_bounds__(256) void softmax_kernel()
{
    __shared__ float red[8];
    __shared__ float bval;
    int row = blockIdx.x;
    int tid = threadIdx.x;
    int lane = tid & 31, wid = tid >> 5;
    float4* p = (float4*)(g_scores + (size_t)row * 1024);
    float4 v = p[tid];
    float mx = fmaxf(fmaxf(v.x, v.y), fmaxf(v.z, v.w));
#pragma unroll
    for (int off = 16; off > 0; off >>= 1)
        mx = fmaxf(mx, __shfl_xor_sync(0xffffffffu, mx, off));
    if (lane == 0) red[wid] = mx;
    __syncthreads();
    if (tid == 0) {
        float m = red[0];
#pragma unroll
        for (int w = 1; w < 8; ++w) m = fmaxf(m, red[w]);
        bval = m;
    }
    __syncthreads();
    float m = bval;
    v.x = expf(v.x - m); v.y = expf(v.y - m);
    v.z = expf(v.z - m); v.w = expf(v.w - m);
    float s = v.x + v.y + v.z + v.w;
#pragma unroll
    for (int off = 16; off > 0; off >>= 1)
        s += __shfl_xor_sync(0xffffffffu, s, off);
    if (lane == 0) red[wid] = s;
    __syncthreads();
    if (tid == 0) {
        float t = 0.f;
#pragma unroll
        for (int w = 0; w < 8; ++w) t += red[w];
        bval = 1.0f / t;
    }
    __syncthreads();
    float inv = bval;
    v.x *= inv; v.y *= inv; v.z *= inv; v.w *= inv;
    p[tid] = v;
}

// ---------------- out = P @ V + band(rel_v), store to g_att [B,T,CH] ----------
__global__ __launch_bounds__(256) void pv_kernel(const float* __restrict__ erv)
{
    __shared__ float Ps[64][68];   // [j][i]
    __shared__ float Vs[64][68];   // [j][d]
    __shared__ float es[576];
    int bh = blockIdx.y;
    int i0 = blockIdx.x * 64;
    int tid = threadIdx.x;
    for (int u = tid; u < 576; u += 256) es[u] = erv[u];
    int ti = tid >> 4, tj = tid & 15;
    float acc[4][4];
#pragma unroll
    for (int a = 0; a < 4; ++a)
#pragma unroll
        for (int b = 0; b < 4; ++b) acc[a][b] = 0.f;

    for (int j0 = 0; j0 < 1024; j0 += 64) {
#pragma unroll
        for (int u = 0; u < 16; ++u) {
            int lin = tid + u * 256;
            int r = lin >> 6, cc = lin & 63;
            Ps[cc][r] = g_scores[((bh * 1024 + i0 + r) << 10) + j0 + cc]; // [j][i]
            Vs[r][cc] = g_v[(bh * 1024 + j0 + r) * 64 + cc];              // [j][d]
        }
        __syncthreads();
#pragma unroll 8
        for (int j = 0; j < 64; ++j) {
            float4 a4 = *(const float4*)&Ps[j][ti * 4];
            float4 b4 = *(const float4*)&Vs[j][tj * 4];
            float av[4] = {a4.x, a4.y, a4.z, a4.w};
            float bv[4] = {b4.x, b4.y, b4.z, b4.w};
#pragma unroll
            for (int a = 0; a < 4; ++a)
#pragma unroll
                for (int b = 0; b < 4; ++b)
                    acc[a][b] += av[a] * bv[b];
        }
        __syncthreads();
    }

    int bb = bh >> 4, hh = bh & 15;
#pragma unroll
    for (int a = 0; a < 4; ++a) {
        int i = i0 + ti * 4 + a;
        const float* prow = g_scores + ((size_t)(bh * 1024 + i) << 10);
#pragma unroll
        for (int u = 0; u < 9; ++u) {
            int j2 = i + u - WIN_;
            if (j2 >= 0 && j2 < 1024) {
                float pv = prow[j2];
#pragma unroll
                for (int b = 0; b < 4; ++b)
                    acc[a][b] += pv * es[u * 64 + tj * 4 + b];
            }
        }
#pragma unroll
        for (int b = 0; b < 4; ++b)
            g_att[(bb * 1024 + i) * 1024 + hh * 64 + tj * 4 + b] = acc[a][b];
    }
}

// --------------------------------- launch --------------------------------------
extern "C" void kernel_launch(void* const* d_in, const int* in_sizes, int n_in,
                              void* d_out, int out_size)
{
    const float* x   = (const float*)d_in[0];
    const float* c   = (const float*)d_in[1];
    const int*   msk = (const int*)  d_in[2];
    const float* Wq  = (const float*)d_in[3];
    const float* bq  = (const float*)d_in[4];
    const float* Wk  = (const float*)d_in[5];
    const float* bk  = (const float*)d_in[6];
    const float* Wv  = (const float*)d_in[7];
    const float* bv  = (const float*)d_in[8];
    const float* Wo  = (const float*)d_in[9];
    const float* bo  = (const float*)d_in[10];
    const float* erk = (const float*)d_in[11];
    const float* erv = (const float*)d_in[12];
    float* out = (float*)d_out;

    dim3 gg(16, 16);
    gemm_kernel<<<gg, 256>>>(x, Wq, bq, 0.125f, nullptr, 0);  // q (pre-scaled)
    gemm_kernel<<<gg, 256>>>(c, Wk, bk, 1.0f,   nullptr, 1);  // k
    gemm_kernel<<<gg, 256>>>(c, Wv, bv, 1.0f,   nullptr, 2);  // v
    rl_kernel<<<BHT / 8, 256>>>(erk);
    scores_kernel<<<dim3(16, 16, B_ * H_), 256>>>(msk);
    softmax_kernel<<<BHT, 256>>>();
    pv_kernel<<<dim3(16, B_ * H_), 256>>>(erv);
    gemm_kernel<<<gg, 256>>>(nullptr, Wo, bo, 1.0f, out, 3);  // final projection
}

// round 3
// speedup vs baseline: 1.4125x; 1.4125x over previous
#include <cuda_runtime.h>
#include <cuda_bf16.h>
#include <cstdint>

// Problem constants
#define B_   2
#define T_   1024
#define CH_  1024
#define H_   16
#define KC_  64
#define WIN_ 4
#define MROWS (B_ * T_)          // 2048
#define BHT  (B_ * H_ * T_)      // 32768

// ---------------- scratch (static device globals; no allocation) ----------------
__device__ float g_q[B_ * H_ * T_ * KC_];     // [B,H,T,KC], pre-scaled by 1/sqrt(KC)
__device__ float g_k[B_ * H_ * T_ * KC_];
__device__ float g_v[B_ * H_ * T_ * KC_];
__device__ float g_rl[BHT * 9];               // qs . emb_rel_k[u], u=0..8
__device__ float g_scores[B_ * H_ * T_ * T_]; // scores, then softmax in place

// bf16 split operands for tensor-core GEMMs
__device__ __nv_bfloat16 gx_hi[MROWS * CH_];
__device__ __nv_bfloat16 gx_lo[MROWS * CH_];
__device__ __nv_bfloat16 gc_hi[MROWS * CH_];
__device__ __nv_bfloat16 gc_lo[MROWS * CH_];
__device__ __nv_bfloat16 gw_hi[4 * CH_ * CH_];   // W^T concat [q|k|v|o]: [4096][1024]
__device__ __nv_bfloat16 gw_lo[4 * CH_ * CH_];
__device__ __nv_bfloat16 g_att_hi[MROWS * CH_];  // attention out, bf16 split
__device__ __nv_bfloat16 g_att_lo[MROWS * CH_];
__device__ float g_bias[4 * CH_];                // [bq|bk|bv|bo]

// ======================= conversion kernels ====================================
__global__ __launch_bounds__(256) void conv_in(
    const float* __restrict__ x, const float* __restrict__ c,
    const float* __restrict__ bq, const float* __restrict__ bk,
    const float* __restrict__ bv, const float* __restrict__ bo)
{
    int i = blockIdx.x * 256 + threadIdx.x;   // float4 index, 0..1048575
    const float4* src;
    __nv_bfloat162 *dh, *dl;
    int j;
    if (i < 524288) {
        src = (const float4*)x; j = i;
        dh = (__nv_bfloat162*)gx_hi; dl = (__nv_bfloat162*)gx_lo;
    } else {
        src = (const float4*)c; j = i - 524288;
        dh = (__nv_bfloat162*)gc_hi; dl = (__nv_bfloat162*)gc_lo;
    }
    float4 v = src[j];
    __nv_bfloat16 hx = __float2bfloat16_rn(v.x), hy = __float2bfloat16_rn(v.y);
    __nv_bfloat16 hz = __float2bfloat16_rn(v.z), hw = __float2bfloat16_rn(v.w);
    __nv_bfloat16 lx = __float2bfloat16_rn(v.x - __bfloat162float(hx));
    __nv_bfloat16 ly = __float2bfloat16_rn(v.y - __bfloat162float(hy));
    __nv_bfloat16 lz = __float2bfloat16_rn(v.z - __bfloat162float(hz));
    __nv_bfloat16 lw = __float2bfloat16_rn(v.w - __bfloat162float(hw));
    dh[2 * j]     = __halves2bfloat162(hx, hy);
    dh[2 * j + 1] = __halves2bfloat162(hz, hw);
    dl[2 * j]     = __halves2bfloat162(lx, ly);
    dl[2 * j + 1] = __halves2bfloat162(lz, lw);
    if (i < 4096) {
        float b = (i < 1024) ? bq[i] : (i < 2048) ? bk[i - 1024]
                : (i < 3072) ? bv[i - 2048] : bo[i - 3072];
        g_bias[i] = b;
    }
}

__global__ __launch_bounds__(256) void conv_w(
    const float* __restrict__ Wq, const float* __restrict__ Wk,
    const float* __restrict__ Wv, const float* __restrict__ Wo)
{
    __shared__ float tile[32][33];
    int z = blockIdx.z;
    const float* W = (z == 0) ? Wq : (z == 1) ? Wk : (z == 2) ? Wv : Wo;
    int n0 = blockIdx.x * 32, k0 = blockIdx.y * 32;
    int tx = threadIdx.x & 31, ty = threadIdx.x >> 5;
#pragma unroll
    for (int u = 0; u < 4; ++u) {
        int k = k0 + ty + u * 8;
        tile[ty + u * 8][tx] = W[k * 1024 + n0 + tx];
    }
    __syncthreads();
#pragma unroll
    for (int u = 0; u < 4; ++u) {
        int r = ty + u * 8;
        float v = tile[tx][r];               // = W[k0+tx][n0+r]
        int dst = (z * 1024 + n0 + r) * 1024 + k0 + tx;
        __nv_bfloat16 h = __float2bfloat16_rn(v);
        gw_hi[dst] = h;
        gw_lo[dst] = __float2bfloat16_rn(v - __bfloat162float(h));
    }
}

// ======================= mma.sync bf16-split GEMM ==============================
__device__ __forceinline__ void mma16816(float* c, const uint32_t* a, const uint32_t* b)
{
    asm volatile(
        "mma.sync.aligned.m16n8k16.row.col.f32.bf16.bf16.f32 "
        "{%0,%1,%2,%3}, {%4,%5,%6,%7}, {%8,%9}, {%0,%1,%2,%3};"
        : "+f"(c[0]), "+f"(c[1]), "+f"(c[2]), "+f"(c[3])
        : "r"(a[0]), "r"(a[1]), "r"(a[2]), "r"(a[3]), "r"(b[0]), "r"(b[1]));
}

// C[2048,1024(slice)] = scale * (A @ W_z^T + bias_z)
// mode 0: grid(8,16,3), z = blockIdx.z selects q/k/v; A = x (z=0) else c.
//         Output scattered to g_q/g_k/g_v layout [B,H,T,KC]; q scaled by 0.125.
// mode 1: grid(8,16,1), z=3; A = g_att split; out = finalout row-major.
#define LDK 72          // padded k-stride (bf16 elems); 144B, conflict-free rows
#define GEMM_SMEM (4 * 128 * LDK * 2)   // 73728 bytes
__global__ __launch_bounds__(256) void gemm_mma(int mode, float* __restrict__ finalout)
{
    extern __shared__ __nv_bfloat16 sm[];
    __nv_bfloat16 (*Ah)[LDK] = (__nv_bfloat16(*)[LDK])(sm);
    __nv_bfloat16 (*Al)[LDK] = (__nv_bfloat16(*)[LDK])(sm + 128 * LDK);
    __nv_bfloat16 (*Bh)[LDK] = (__nv_bfloat16(*)[LDK])(sm + 2 * 128 * LDK);
    __nv_bfloat16 (*Bl)[LDK] = (__nv_bfloat16(*)[LDK])(sm + 3 * 128 * LDK);

    int tid = threadIdx.x;
    int wid = tid >> 5, lane = tid & 31;
    int g = lane >> 2, tg = lane & 3;
    int warp_m = wid & 1, warp_n = wid >> 1;   // 2 x 4 warp grid; tile 64x32
    int z = (mode == 0) ? (int)blockIdx.z : 3;

    const __nv_bfloat16 *A_hi, *A_lo;
    if (mode == 0) {
        if (z == 0) { A_hi = gx_hi; A_lo = gx_lo; }
        else        { A_hi = gc_hi; A_lo = gc_lo; }
    } else { A_hi = g_att_hi; A_lo = g_att_lo; }
    int arow0 = blockIdx.y * 128;
    int brow0 = z * 1024 + blockIdx.x * 128;

    float acc[4][4][4];
#pragma unroll
    for (int mi = 0; mi < 4; ++mi)
#pragma unroll
        for (int ni = 0; ni < 4; ++ni)
#pragma unroll
            for (int e = 0; e < 4; ++e) acc[mi][ni][e] = 0.f;

    for (int k0 = 0; k0 < 1024; k0 += 64) {
        // load 4 tiles: each 128 rows x 64 k (bf16)
#pragma unroll
        for (int u = 0; u < 4; ++u) {
            int lin = tid + u * 256;          // 0..1023
            int r = lin >> 3, c8 = lin & 7;
            *(uint4*)&Ah[r][c8 * 8] = *(const uint4*)(A_hi + (size_t)(arow0 + r) * 1024 + k0 + c8 * 8);
            *(uint4*)&Al[r][c8 * 8] = *(const uint4*)(A_lo + (size_t)(arow0 + r) * 1024 + k0 + c8 * 8);
            *(uint4*)&Bh[r][c8 * 8] = *(const uint4*)(gw_hi + (size_t)(brow0 + r) * 1024 + k0 + c8 * 8);
            *(uint4*)&Bl[r][c8 * 8] = *(const uint4*)(gw_lo + (size_t)(brow0 + r) * 1024 + k0 + c8 * 8);
        }
        __syncthreads();

#pragma unroll
        for (int kk = 0; kk < 4; ++kk) {      // 4 x k16 chunks
            int kof = kk * 16 + 2 * tg;
            uint32_t ah[4][4], al[4][4], bh[4][2], bl[4][2];
#pragma unroll
            for (int mi = 0; mi < 4; ++mi) {
                int row = warp_m * 64 + mi * 16 + g;
                ah[mi][0] = *(const uint32_t*)&Ah[row][kof];
                ah[mi][1] = *(const uint32_t*)&Ah[row + 8][kof];
                ah[mi][2] = *(const uint32_t*)&Ah[row][kof + 8];
                ah[mi][3] = *(const uint32_t*)&Ah[row + 8][kof + 8];
                al[mi][0] = *(const uint32_t*)&Al[row][kof];
                al[mi][1] = *(const uint32_t*)&Al[row + 8][kof];
                al[mi][2] = *(const uint32_t*)&Al[row][kof + 8];
                al[mi][3] = *(const uint32_t*)&Al[row + 8][kof + 8];
            }
#pragma unroll
            for (int ni = 0; ni < 4; ++ni) {
                int col = warp_n * 32 + ni * 8 + g;
                bh[ni][0] = *(const uint32_t*)&Bh[col][kof];
                bh[ni][1] = *(const uint32_t*)&Bh[col][kof + 8];
                bl[ni][0] = *(const uint32_t*)&Bl[col][kof];
                bl[ni][1] = *(const uint32_t*)&Bl[col][kof + 8];
            }
#pragma unroll
            for (int mi = 0; mi < 4; ++mi)
#pragma unroll
                for (int ni = 0; ni < 4; ++ni) {
                    mma16816(acc[mi][ni], ah[mi], bh[ni]);
                    mma16816(acc[mi][ni], ah[mi], bl[ni]);
                    mma16816(acc[mi][ni], al[mi], bh[ni]);
                }
        }
        __syncthreads();
    }

    // ---------------- epilogue ----------------
    float scale = (mode == 0 && z == 0) ? 0.125f : 1.0f;
    float* dstg = (mode == 1) ? finalout : (z == 0) ? g_q : (z == 1) ? g_k : g_v;
#pragma unroll
    for (int mi = 0; mi < 4; ++mi) {
#pragma unroll
        for (int ni = 0; ni < 4; ++ni) {
#pragma unroll
            for (int e = 0; e < 4; ++e) {
                int row = blockIdx.y * 128 + warp_m * 64 + mi * 16 + g + ((e >> 1) ? 8 : 0);
                int col = blockIdx.x * 128 + warp_n * 32 + ni * 8 + 2 * tg + (e & 1);
                float v = (acc[mi][ni][e] + g_bias[z * 1024 + col]) * scale;
                if (mode == 0) {
                    int h = col >> 6, bb = row >> 10, t = row & 1023, d = col & 63;
                    dstg[(((bb * 16 + h) << 16) | (t << 6)) + d] = v;
                } else {
                    dstg[(size_t)row * 1024 + col] = v;
                }
            }
        }
    }
}

// ---------------- rel-key logits: g_rl[row][u] = g_q[row,:] . erk[u,:] -------------
__global__ __launch_bounds__(256) void rl_kernel(const float* __restrict__ erk)
{
    __shared__ float e[9 * 64];
    int tid = threadIdx.x;
    for (int u = tid; u < 576; u += 256) e[u] = erk[u];
    __syncthreads();
    int warp = tid >> 5, lane = tid & 31;
    int row = blockIdx.x * 8 + warp;
    const float* q = g_q + row * 64;
    float q0 = q[lane], q1 = q[lane + 32];
#pragma unroll
    for (int u = 0; u < 9; ++u) {
        float s = q0 * e[u * 64 + lane] + q1 * e[u * 64 + lane + 32];
#pragma unroll
        for (int off = 16; off > 0; off >>= 1)
            s += __shfl_xor_sync(0xffffffffu, s, off);
        if (lane == 0) g_rl[row * 9 + u] = s;
    }
}

// ---------------- scores: S = Qs @ K^T + band(rel_k) , mask --------------------
__global__ __launch_bounds__(256) void scores_kernel(const int* __restrict__ mask)
{
    __shared__ float Qs[64][68];
    __shared__ float Ks[64][68];
    int bh = blockIdx.z;
    int i0 = blockIdx.y * 64, j0 = blockIdx.x * 64;
    int tid = threadIdx.x;
    const float* qp = g_q + (bh * 1024 + i0) * 64;
    const float* kp = g_k + (bh * 1024 + j0) * 64;
#pragma unroll
    for (int u = 0; u < 16; ++u) {
        int lin = tid + u * 256;
        int r = lin >> 6, dd = lin & 63;
        Qs[dd][r] = qp[r * 64 + dd];
        Ks[dd][r] = kp[r * 64 + dd];
    }
    __syncthreads();
    int ti = tid >> 4, tj = tid & 15;
    float acc[4][4];
#pragma unroll
    for (int a = 0; a < 4; ++a)
#pragma unroll
        for (int b = 0; b < 4; ++b) acc[a][b] = 0.f;
#pragma unroll 8
    for (int kk = 0; kk < 64; ++kk) {
        float4 a4 = *(const float4*)&Qs[kk][ti * 4];
        float4 b4 = *(const float4*)&Ks[kk][tj * 4];
        float av[4] = {a4.x, a4.y, a4.z, a4.w};
        float bv[4] = {b4.x, b4.y, b4.z, b4.w};
#pragma unroll
        for (int a = 0; a < 4; ++a)
#pragma unroll
            for (int b = 0; b < 4; ++b)
                acc[a][b] += av[a] * bv[b];
    }
    int bb = bh >> 4;
#pragma unroll
    for (int a = 0; a < 4; ++a) {
        int i = i0 + ti * 4 + a;
#pragma unroll
        for (int b = 0; b < 4; ++b) {
            int j = j0 + tj * 4 + b;
            float s = acc[a][b];
            int d = j - i;
            if (d >= -WIN_ && d <= WIN_)
                s += g_rl[(bh * 1024 + i) * 9 + d + WIN_];
            if (mask[(bb * 1024 + i) * 1024 + j] == 0) s = 1e-4f;
            g_scores[((bh * 1024 + i) << 10) + j] = s;
        }
    }
}

// ---------------- softmax in place over rows of g_scores ----------------------
__global__ __launch_bounds__(256) void softmax_kernel()
{
    __shared__ float red[8];
    __shared__ float bval;
    int row = blockIdx.x;
    int tid = threadIdx.x;
    int lane = tid & 31, wid = tid >> 5;
    float4* p = (float4*)(g_scores + (size_t)row * 1024);
    float4 v = p[tid];
    float mx = fmaxf(fmaxf(v.x, v.y), fmaxf(v.z, v.w));
#pragma unroll
    for (int off = 16; off > 0; off >>= 1)
        mx = fmaxf(mx, __shfl_xor_sync(0xffffffffu, mx, off));
    if (lane == 0) red[wid] = mx;
    __syncthreads();
    if (tid == 0) {
        float m = red[0];
#pragma unroll
        for (int w = 1; w < 8; ++w) m = fmaxf(m, red[w]);
        bval = m;
    }
    __syncthreads();
    float m = bval;
    v.x = expf(v.x - m); v.y = expf(v.y - m);
    v.z = expf(v.z - m); v.w = expf(v.w - m);
    float s = v.x + v.y + v.z + v.w;
#pragma unroll
    for (int off = 16; off > 0; off >>= 1)
        s += __shfl_xor_sync(0xffffffffu, s, off);
    if (lane == 0) red[wid] = s;
    __syncthreads();
    if (tid == 0) {
        float t = 0.f;
#pragma unroll
        for (int w = 0; w < 8; ++w) t += red[w];
        bval = 1.0f / t;
    }
    __syncthreads();
    float inv = bval;
    v.x *= inv; v.y *= inv; v.z *= inv; v.w *= inv;
    p[tid] = v;
}

// ---------------- out = P @ V + band(rel_v), store bf16-split g_att ----------
__global__ __launch_bounds__(256) void pv_kernel(const float* __restrict__ erv)
{
    __shared__ float Ps[64][68];
    __shared__ float Vs[64][68];
    __shared__ float es[576];
    int bh = blockIdx.y;
    int i0 = blockIdx.x * 64;
    int tid = threadIdx.x;
    for (int u = tid; u < 576; u += 256) es[u] = erv[u];
    int ti = tid >> 4, tj = tid & 15;
    float acc[4][4];
#pragma unroll
    for (int a = 0; a < 4; ++a)
#pragma unroll
        for (int b = 0; b < 4; ++b) acc[a][b] = 0.f;

    for (int j0 = 0; j0 < 1024; j0 += 64) {
#pragma unroll
        for (int u = 0; u < 16; ++u) {
            int lin = tid + u * 256;
            int r = lin >> 6, cc = lin & 63;
            Ps[cc][r] = g_scores[((bh * 1024 + i0 + r) << 10) + j0 + cc];
            Vs[r][cc] = g_v[(bh * 1024 + j0 + r) * 64 + cc];
        }
        __syncthreads();
#pragma unroll 8
        for (int j = 0; j < 64; ++j) {
            float4 a4 = *(const float4*)&Ps[j][ti * 4];
            float4 b4 = *(const float4*)&Vs[j][tj * 4];
            float av[4] = {a4.x, a4.y, a4.z, a4.w};
            float bv[4] = {b4.x, b4.y, b4.z, b4.w};
#pragma unroll
            for (int a = 0; a < 4; ++a)
#pragma unroll
                for (int b = 0; b < 4; ++b)
                    acc[a][b] += av[a] * bv[b];
        }
        __syncthreads();
    }

    int bb = bh >> 4, hh = bh & 15;
#pragma unroll
    for (int a = 0; a < 4; ++a) {
        int i = i0 + ti * 4 + a;
        const float* prow = g_scores + ((size_t)(bh * 1024 + i) << 10);
#pragma unroll
        for (int u = 0; u < 9; ++u) {
            int j2 = i + u - WIN_;
            if (j2 >= 0 && j2 < 1024) {
                float pv = prow[j2];
#pragma unroll
                for (int b = 0; b < 4; ++b)
                    acc[a][b] += pv * es[u * 64 + tj * 4 + b];
            }
        }
        int baseidx = (bb * 1024 + i) * 1024 + hh * 64 + tj * 4;
        __nv_bfloat16 h0 = __float2bfloat16_rn(acc[a][0]);
        __nv_bfloat16 h1 = __float2bfloat16_rn(acc[a][1]);
        __nv_bfloat16 h2 = __float2bfloat16_rn(acc[a][2]);
        __nv_bfloat16 h3 = __float2bfloat16_rn(acc[a][3]);
        __nv_bfloat16 l0 = __float2bfloat16_rn(acc[a][0] - __bfloat162float(h0));
        __nv_bfloat16 l1 = __float2bfloat16_rn(acc[a][1] - __bfloat162float(h1));
        __nv_bfloat16 l2 = __float2bfloat16_rn(acc[a][2] - __bfloat162float(h2));
        __nv_bfloat16 l3 = __float2bfloat16_rn(acc[a][3] - __bfloat162float(h3));
        *(__nv_bfloat162*)(g_att_hi + baseidx)     = __halves2bfloat162(h0, h1);
        *(__nv_bfloat162*)(g_att_hi + baseidx + 2) = __halves2bfloat162(h2, h3);
        *(__nv_bfloat162*)(g_att_lo + baseidx)     = __halves2bfloat162(l0, l1);
        *(__nv_bfloat162*)(g_att_lo + baseidx + 2) = __halves2bfloat162(l2, l3);
    }
}

// --------------------------------- launch --------------------------------------
extern "C" void kernel_launch(void* const* d_in, const int* in_sizes, int n_in,
                              void* d_out, int out_size)
{
    const float* x   = (const float*)d_in[0];
    const float* c   = (const float*)d_in[1];
    const int*   msk = (const int*)  d_in[2];
    const float* Wq  = (const float*)d_in[3];
    const float* bq  = (const float*)d_in[4];
    const float* Wk  = (const float*)d_in[5];
    const float* bk  = (const float*)d_in[6];
    const float* Wv  = (const float*)d_in[7];
    const float* bv  = (const float*)d_in[8];
    const float* Wo  = (const float*)d_in[9];
    const float* bo  = (const float*)d_in[10];
    const float* erk = (const float*)d_in[11];
    const float* erv = (const float*)d_in[12];
    float* out = (float*)d_out;

    static int smem_set = 0;
    if (!smem_set) {
        cudaFuncSetAttribute(gemm_mma, cudaFuncAttributeMaxDynamicSharedMemorySize, GEMM_SMEM);
        smem_set = 1;
    }

    conv_in<<<4096, 256>>>(x, c, bq, bk, bv, bo);
    conv_w<<<dim3(32, 32, 4), 256>>>(Wq, Wk, Wv, Wo);
    gemm_mma<<<dim3(8, 16, 3), 256, GEMM_SMEM>>>(0, nullptr);   // Q,K,V
    rl_kernel<<<BHT / 8, 256>>>(erk);
    scores_kernel<<<dim3(16, 16, B_ * H_), 256>>>(msk);
    softmax_kernel<<<BHT, 256>>>();
    pv_kernel<<<dim3(16, B_ * H_), 256>>>(erv);
    gemm_mma<<<dim3(8, 16, 1), 256, GEMM_SMEM>>>(1, out);       // @Wo + bo
}

// round 4
// speedup vs baseline: 2.2936x; 1.6238x over previous
#include <cuda_runtime.h>
#include <cuda_bf16.h>
#include <cstdint>

// Problem constants
#define B_   2
#define T_   1024
#define CH_  1024
#define H_   16
#define KC_  64
#define WIN_ 4
#define MROWS (B_ * T_)          // 2048
#define BHT  (B_ * H_ * T_)      // 32768

// ---------------- scratch (static device globals; no allocation) ----------------
__device__ float g_q[B_ * H_ * T_ * KC_];     // [B,H,T,KC], pre-scaled by 1/sqrt(KC)
__device__ float g_k[B_ * H_ * T_ * KC_];
__device__ float g_v[B_ * H_ * T_ * KC_];
__device__ float g_rl[BHT * 9];               // qs . emb_rel_k[u], u=0..8

// bf16 split operands for tensor-core GEMMs
__device__ __nv_bfloat16 gx_hi[MROWS * CH_];
__device__ __nv_bfloat16 gx_lo[MROWS * CH_];
__device__ __nv_bfloat16 gc_hi[MROWS * CH_];
__device__ __nv_bfloat16 gc_lo[MROWS * CH_];
__device__ __nv_bfloat16 gw_hi[4 * CH_ * CH_];   // W^T concat [q|k|v|o]: [4096][1024]
__device__ __nv_bfloat16 gw_lo[4 * CH_ * CH_];
__device__ __nv_bfloat16 g_att_hi[MROWS * CH_];  // attention out, bf16 split
__device__ __nv_bfloat16 g_att_lo[MROWS * CH_];
__device__ float g_bias[4 * CH_];                // [bq|bk|bv|bo]

// ======================= helpers ================================================
__device__ __forceinline__ void mma16816(float* c, const uint32_t* a, const uint32_t* b)
{
    asm volatile(
        "mma.sync.aligned.m16n8k16.row.col.f32.bf16.bf16.f32 "
        "{%0,%1,%2,%3}, {%4,%5,%6,%7}, {%8,%9}, {%0,%1,%2,%3};"
        : "+f"(c[0]), "+f"(c[1]), "+f"(c[2]), "+f"(c[3])
        : "r"(a[0]), "r"(a[1]), "r"(a[2]), "r"(a[3]), "r"(b[0]), "r"(b[1]));
}

__device__ __forceinline__ void splitbf(float x, __nv_bfloat16& h, __nv_bfloat16& l)
{
    h = __float2bfloat16_rn(x);
    l = __float2bfloat16_rn(x - __bfloat162float(h));
}

__device__ __forceinline__ void split_pack(float x, float y, uint32_t& hi, uint32_t& lo)
{
    __nv_bfloat16 hx, lx, hy, ly;
    splitbf(x, hx, lx); splitbf(y, hy, ly);
    __nv_bfloat162 th = __halves2bfloat162(hx, hy);
    __nv_bfloat162 tl = __halves2bfloat162(lx, ly);
    hi = *reinterpret_cast<uint32_t*>(&th);
    lo = *reinterpret_cast<uint32_t*>(&tl);
}

// ======================= conversion kernels ====================================
__global__ __launch_bounds__(256) void conv_in(
    const float* __restrict__ x, const float* __restrict__ c,
    const float* __restrict__ bq, const float* __restrict__ bk,
    const float* __restrict__ bv, const float* __restrict__ bo)
{
    int i = blockIdx.x * 256 + threadIdx.x;   // float4 index, 0..1048575
    const float4* src;
    __nv_bfloat162 *dh, *dl;
    int j;
    if (i < 524288) {
        src = (const float4*)x; j = i;
        dh = (__nv_bfloat162*)gx_hi; dl = (__nv_bfloat162*)gx_lo;
    } else {
        src = (const float4*)c; j = i - 524288;
        dh = (__nv_bfloat162*)gc_hi; dl = (__nv_bfloat162*)gc_lo;
    }
    float4 v = src[j];
    __nv_bfloat16 hx, lx, hy, ly, hz, lz, hw, lw;
    splitbf(v.x, hx, lx); splitbf(v.y, hy, ly);
    splitbf(v.z, hz, lz); splitbf(v.w, hw, lw);
    dh[2 * j]     = __halves2bfloat162(hx, hy);
    dh[2 * j + 1] = __halves2bfloat162(hz, hw);
    dl[2 * j]     = __halves2bfloat162(lx, ly);
    dl[2 * j + 1] = __halves2bfloat162(lz, lw);
    if (i < 4096) {
        float b = (i < 1024) ? bq[i] : (i < 2048) ? bk[i - 1024]
                : (i < 3072) ? bv[i - 2048] : bo[i - 3072];
        g_bias[i] = b;
    }
}

__global__ __launch_bounds__(256) void conv_w(
    const float* __restrict__ Wq, const float* __restrict__ Wk,
    const float* __restrict__ Wv, const float* __restrict__ Wo)
{
    __shared__ float tile[32][33];
    int z = blockIdx.z;
    const float* W = (z == 0) ? Wq : (z == 1) ? Wk : (z == 2) ? Wv : Wo;
    int n0 = blockIdx.x * 32, k0 = blockIdx.y * 32;
    int tx = threadIdx.x & 31, ty = threadIdx.x >> 5;
#pragma unroll
    for (int u = 0; u < 4; ++u) {
        int k = k0 + ty + u * 8;
        tile[ty + u * 8][tx] = W[k * 1024 + n0 + tx];
    }
    __syncthreads();
#pragma unroll
    for (int u = 0; u < 4; ++u) {
        int r = ty + u * 8;
        float v = tile[tx][r];               // = W[k0+tx][n0+r]
        int dst = (z * 1024 + n0 + r) * 1024 + k0 + tx;
        __nv_bfloat16 h, l;
        splitbf(v, h, l);
        gw_hi[dst] = h;
        gw_lo[dst] = l;
    }
}

// ======================= mma.sync bf16-split GEMM ==============================
#define LDK 72          // padded k-stride (bf16 elems)
#define GEMM_SMEM (4 * 128 * LDK * 2)   // 73728 bytes
__global__ __launch_bounds__(256) void gemm_mma(int mode, float* __restrict__ finalout)
{
    extern __shared__ __nv_bfloat16 sm[];
    __nv_bfloat16 (*Ah)[LDK] = (__nv_bfloat16(*)[LDK])(sm);
    __nv_bfloat16 (*Al)[LDK] = (__nv_bfloat16(*)[LDK])(sm + 128 * LDK);
    __nv_bfloat16 (*Bh)[LDK] = (__nv_bfloat16(*)[LDK])(sm + 2 * 128 * LDK);
    __nv_bfloat16 (*Bl)[LDK] = (__nv_bfloat16(*)[LDK])(sm + 3 * 128 * LDK);

    int tid = threadIdx.x;
    int wid = tid >> 5, lane = tid & 31;
    int g = lane >> 2, tg = lane & 3;
    int warp_m = wid & 1, warp_n = wid >> 1;
    int z = (mode == 0) ? (int)blockIdx.z : 3;

    const __nv_bfloat16 *A_hi, *A_lo;
    if (mode == 0) {
        if (z == 0) { A_hi = gx_hi; A_lo = gx_lo; }
        else        { A_hi = gc_hi; A_lo = gc_lo; }
    } else { A_hi = g_att_hi; A_lo = g_att_lo; }
    int arow0 = blockIdx.y * 128;
    int brow0 = z * 1024 + blockIdx.x * 128;

    float acc[4][4][4];
#pragma unroll
    for (int mi = 0; mi < 4; ++mi)
#pragma unroll
        for (int ni = 0; ni < 4; ++ni)
#pragma unroll
            for (int e = 0; e < 4; ++e) acc[mi][ni][e] = 0.f;

    for (int k0 = 0; k0 < 1024; k0 += 64) {
#pragma unroll
        for (int u = 0; u < 4; ++u) {
            int lin = tid + u * 256;
            int r = lin >> 3, c8 = lin & 7;
            *(uint4*)&Ah[r][c8 * 8] = *(const uint4*)(A_hi + (size_t)(arow0 + r) * 1024 + k0 + c8 * 8);
            *(uint4*)&Al[r][c8 * 8] = *(const uint4*)(A_lo + (size_t)(arow0 + r) * 1024 + k0 + c8 * 8);
            *(uint4*)&Bh[r][c8 * 8] = *(const uint4*)(gw_hi + (size_t)(brow0 + r) * 1024 + k0 + c8 * 8);
            *(uint4*)&Bl[r][c8 * 8] = *(const uint4*)(gw_lo + (size_t)(brow0 + r) * 1024 + k0 + c8 * 8);
        }
        __syncthreads();

#pragma unroll
        for (int kk = 0; kk < 4; ++kk) {
            int kof = kk * 16 + 2 * tg;
            uint32_t ah[4][4], al[4][4], bh[4][2], bl[4][2];
#pragma unroll
            for (int mi = 0; mi < 4; ++mi) {
                int row = warp_m * 64 + mi * 16 + g;
                ah[mi][0] = *(const uint32_t*)&Ah[row][kof];
                ah[mi][1] = *(const uint32_t*)&Ah[row + 8][kof];
                ah[mi][2] = *(const uint32_t*)&Ah[row][kof + 8];
                ah[mi][3] = *(const uint32_t*)&Ah[row + 8][kof + 8];
                al[mi][0] = *(const uint32_t*)&Al[row][kof];
                al[mi][1] = *(const uint32_t*)&Al[row + 8][kof];
                al[mi][2] = *(const uint32_t*)&Al[row][kof + 8];
                al[mi][3] = *(const uint32_t*)&Al[row + 8][kof + 8];
            }
#pragma unroll
            for (int ni = 0; ni < 4; ++ni) {
                int col = warp_n * 32 + ni * 8 + g;
                bh[ni][0] = *(const uint32_t*)&Bh[col][kof];
                bh[ni][1] = *(const uint32_t*)&Bh[col][kof + 8];
                bl[ni][0] = *(const uint32_t*)&Bl[col][kof];
                bl[ni][1] = *(const uint32_t*)&Bl[col][kof + 8];
            }
#pragma unroll
            for (int mi = 0; mi < 4; ++mi)
#pragma unroll
                for (int ni = 0; ni < 4; ++ni) {
                    mma16816(acc[mi][ni], ah[mi], bh[ni]);
                    mma16816(acc[mi][ni], ah[mi], bl[ni]);
                    mma16816(acc[mi][ni], al[mi], bh[ni]);
                }
        }
        __syncthreads();
    }

    float scale = (mode == 0 && z == 0) ? 0.125f : 1.0f;
    float* dstg = (mode == 1) ? finalout : (z == 0) ? g_q : (z == 1) ? g_k : g_v;
#pragma unroll
    for (int mi = 0; mi < 4; ++mi) {
#pragma unroll
        for (int ni = 0; ni < 4; ++ni) {
#pragma unroll
            for (int e = 0; e < 4; ++e) {
                int row = blockIdx.y * 128 + warp_m * 64 + mi * 16 + g + ((e >> 1) ? 8 : 0);
                int col = blockIdx.x * 128 + warp_n * 32 + ni * 8 + 2 * tg + (e & 1);
                float v = (acc[mi][ni][e] + g_bias[z * 1024 + col]) * scale;
                if (mode == 0) {
                    int h = col >> 6, bb = row >> 10, t = row & 1023, d = col & 63;
                    dstg[(((bb * 16 + h) << 16) | (t << 6)) + d] = v;
                } else {
                    dstg[(size_t)row * 1024 + col] = v;
                }
            }
        }
    }
}

// ---------------- rel-key logits: g_rl[row][u] = g_q[row,:] . erk[u,:] -------------
__global__ __launch_bounds__(256) void rl_kernel(const float* __restrict__ erk)
{
    __shared__ float e[9 * 64];
    int tid = threadIdx.x;
    for (int u = tid; u < 576; u += 256) e[u] = erk[u];
    __syncthreads();
    int warp = tid >> 5, lane = tid & 31;
    int row = blockIdx.x * 8 + warp;
    const float* q = g_q + row * 64;
    float q0 = q[lane], q1 = q[lane + 32];
#pragma unroll
    for (int u = 0; u < 9; ++u) {
        float s = q0 * e[u * 64 + lane] + q1 * e[u * 64 + lane + 32];
#pragma unroll
        for (int off = 16; off > 0; off >>= 1)
            s += __shfl_xor_sync(0xffffffffu, s, off);
        if (lane == 0) g_rl[row * 9 + u] = s;
    }
}

// =================== fused flash attention (scores+softmax+pv+bands) ===========
// grid (8 i-tiles, 32 bh), 256 threads. Smem layout (bytes):
//   QH 0, QL 18432, KH 36864, KL 55296  : [128][72] bf16 each
//   VTH 73728, VTL 91136                : [64][136] bf16 each (v transposed)
//   BAND 108544 : [128][12] f32, RLS 114688 : [128][9] f32, ERVS 119296 : 576 f32
#define ATT_SMEM 121600
__global__ __launch_bounds__(256, 1) void attn_fused(
    const int* __restrict__ mask, const float* __restrict__ erv)
{
    extern __shared__ char smc[];
    __nv_bfloat16 (*QH)[72]  = (__nv_bfloat16(*)[72])(smc);
    __nv_bfloat16 (*QL)[72]  = (__nv_bfloat16(*)[72])(smc + 18432);
    __nv_bfloat16 (*KH)[72]  = (__nv_bfloat16(*)[72])(smc + 36864);
    __nv_bfloat16 (*KL)[72]  = (__nv_bfloat16(*)[72])(smc + 55296);
    __nv_bfloat16 (*VTH)[136] = (__nv_bfloat16(*)[136])(smc + 73728);
    __nv_bfloat16 (*VTL)[136] = (__nv_bfloat16(*)[136])(smc + 91136);
    float (*BAND)[12] = (float(*)[12])(smc + 108544);
    float (*RLS)[9]   = (float(*)[9])(smc + 114688);
    float* ERVS       = (float*)(smc + 119296);

    int tid = threadIdx.x, wid = tid >> 5, lane = tid & 31;
    int g = lane >> 2, tq = lane & 3;
    int bh = blockIdx.y, b = bh >> 4, h = bh & 15;
    int i0 = blockIdx.x * 128;

    // ---- load Q tile (fp32 -> hi/lo bf16), RLS, ERVS, zero BAND ----
    {
        const float4* qsrc = (const float4*)(g_q + ((size_t)bh * 1024 + i0) * 64);
        for (int idx = tid; idx < 2048; idx += 256) {
            int r = idx >> 4, c4 = (idx & 15) * 4;
            float4 v = qsrc[idx];
            __nv_bfloat16 hh, ll;
            splitbf(v.x, hh, ll); QH[r][c4] = hh;     QL[r][c4] = ll;
            splitbf(v.y, hh, ll); QH[r][c4 + 1] = hh; QL[r][c4 + 1] = ll;
            splitbf(v.z, hh, ll); QH[r][c4 + 2] = hh; QL[r][c4 + 2] = ll;
            splitbf(v.w, hh, ll); QH[r][c4 + 3] = hh; QL[r][c4 + 3] = ll;
        }
        const float* rsrc = g_rl + ((size_t)bh * 1024 + i0) * 9;
        for (int idx = tid; idx < 1152; idx += 256) ((float*)RLS)[idx + (idx / 9) * 0] = rsrc[idx];
        for (int idx = tid; idx < 576; idx += 256) ERVS[idx] = erv[idx];
        for (int idx = tid; idx < 128 * 12; idx += 256) ((float*)BAND)[idx] = 0.f;
    }

    float O[8][4];
#pragma unroll
    for (int nd = 0; nd < 8; ++nd)
#pragma unroll
        for (int e = 0; e < 4; ++e) O[nd][e] = 0.f;
    float m0 = -1e30f, m1 = -1e30f, l0 = 0.f, l1 = 0.f;

    const int rbase = wid * 16 + g;

    for (int jt = 0; jt < 8; ++jt) {
        int j0 = jt * 128;
        // ---- fill K (hi/lo) and V^T (hi/lo) ----
        const float4* ksrc = (const float4*)(g_k + ((size_t)bh * 1024 + j0) * 64);
        for (int idx = tid; idx < 2048; idx += 256) {
            int r = idx >> 4, c4 = (idx & 15) * 4;
            float4 v = ksrc[idx];
            __nv_bfloat16 hh, ll;
            splitbf(v.x, hh, ll); KH[r][c4] = hh;     KL[r][c4] = ll;
            splitbf(v.y, hh, ll); KH[r][c4 + 1] = hh; KL[r][c4 + 1] = ll;
            splitbf(v.z, hh, ll); KH[r][c4 + 2] = hh; KL[r][c4 + 2] = ll;
            splitbf(v.w, hh, ll); KH[r][c4 + 3] = hh; KL[r][c4 + 3] = ll;
        }
        {
            int jj = tid >> 1, halfc = tid & 1;
            const float4* vsrc = (const float4*)(g_v + ((size_t)bh * 1024 + j0 + jj) * 64 + halfc * 32);
#pragma unroll
            for (int u = 0; u < 8; ++u) {
                float4 v = vsrc[u];
                int d0 = halfc * 32 + u * 4;
                __nv_bfloat16 hh, ll;
                splitbf(v.x, hh, ll); VTH[d0][jj] = hh;     VTL[d0][jj] = ll;
                splitbf(v.y, hh, ll); VTH[d0 + 1][jj] = hh; VTL[d0 + 1][jj] = ll;
                splitbf(v.z, hh, ll); VTH[d0 + 2][jj] = hh; VTL[d0 + 2][jj] = ll;
                splitbf(v.w, hh, ll); VTH[d0 + 3][jj] = hh; VTL[d0 + 3][jj] = ll;
            }
        }
        __syncthreads();

        // ---- S = Qs K^T (bf16 split, 3 passes) ----
        float S[16][4];
#pragma unroll
        for (int nf = 0; nf < 16; ++nf)
#pragma unroll
            for (int e = 0; e < 4; ++e) S[nf][e] = 0.f;
#pragma unroll
        for (int ks = 0; ks < 4; ++ks) {
            int kof = ks * 16 + 2 * tq;
            uint32_t ah[4], al[4];
            ah[0] = *(const uint32_t*)&QH[rbase][kof];
            ah[1] = *(const uint32_t*)&QH[rbase + 8][kof];
            ah[2] = *(const uint32_t*)&QH[rbase][kof + 8];
            ah[3] = *(const uint32_t*)&QH[rbase + 8][kof + 8];
            al[0] = *(const uint32_t*)&QL[rbase][kof];
            al[1] = *(const uint32_t*)&QL[rbase + 8][kof];
            al[2] = *(const uint32_t*)&QL[rbase][kof + 8];
            al[3] = *(const uint32_t*)&QL[rbase + 8][kof + 8];
#pragma unroll
            for (int nf = 0; nf < 16; ++nf) {
                int col = nf * 8 + g;
                uint32_t bhf[2], blf[2];
                bhf[0] = *(const uint32_t*)&KH[col][kof];
                bhf[1] = *(const uint32_t*)&KH[col][kof + 8];
                blf[0] = *(const uint32_t*)&KL[col][kof];
                blf[1] = *(const uint32_t*)&KL[col][kof + 8];
                mma16816(S[nf], ah, bhf);
                mma16816(S[nf], ah, blf);
                mma16816(S[nf], al, bhf);
            }
        }

        // ---- fixup: rel-k band + mask; row max ----
        float mx0 = -1e30f, mx1 = -1e30f;
        const int* mrow0 = mask + (((size_t)b << 10) + i0 + rbase) * 1024 + j0;
        const int* mrow1 = mrow0 + (size_t)8 * 1024;
#pragma unroll
        for (int nf = 0; nf < 16; ++nf) {
#pragma unroll
            for (int e = 0; e < 4; ++e) {
                int rl_ = rbase + ((e >> 1) << 3);
                int jloc = nf * 8 + 2 * tq + (e & 1);
                float s = S[nf][e];
                int d = (j0 + jloc) - (i0 + rl_);
                if ((unsigned)(d + 4) <= 8u) s += RLS[rl_][d + 4];
                int mv = (e < 2) ? mrow0[jloc] : mrow1[jloc];
                if (mv == 0) s = 1e-4f;
                S[nf][e] = s;
                if (e < 2) mx0 = fmaxf(mx0, s); else mx1 = fmaxf(mx1, s);
            }
        }
        mx0 = fmaxf(mx0, __shfl_xor_sync(0xffffffffu, mx0, 1));
        mx0 = fmaxf(mx0, __shfl_xor_sync(0xffffffffu, mx0, 2));
        mx1 = fmaxf(mx1, __shfl_xor_sync(0xffffffffu, mx1, 1));
        mx1 = fmaxf(mx1, __shfl_xor_sync(0xffffffffu, mx1, 2));
        float mn0 = fmaxf(m0, mx0), mn1 = fmaxf(m1, mx1);
        float a0 = __expf(m0 - mn0), a1 = __expf(m1 - mn1);
        m0 = mn0; m1 = mn1;

        // rescale output acc + band
#pragma unroll
        for (int nd = 0; nd < 8; ++nd) {
            O[nd][0] *= a0; O[nd][1] *= a0; O[nd][2] *= a1; O[nd][3] *= a1;
        }
        if (tq == 0) {
#pragma unroll
            for (int u = 0; u < 9; ++u) {
                BAND[rbase][u] *= a0;
                BAND[rbase + 8][u] *= a1;
            }
        }
        __syncwarp();

        // ---- p = exp(s - m), row sums, band adds ----
        float s0 = 0.f, s1 = 0.f;
#pragma unroll
        for (int nf = 0; nf < 16; ++nf) {
#pragma unroll
            for (int e = 0; e < 4; ++e) {
                float p = __expf(S[nf][e] - ((e < 2) ? mn0 : mn1));
                S[nf][e] = p;
                if (e < 2) s0 += p; else s1 += p;
                int rl_ = rbase + ((e >> 1) << 3);
                int d = (j0 + nf * 8 + 2 * tq + (e & 1)) - (i0 + rl_);
                if ((unsigned)(d + 4) <= 8u) BAND[rl_][d + 4] += p;
            }
        }
        s0 += __shfl_xor_sync(0xffffffffu, s0, 1);
        s0 += __shfl_xor_sync(0xffffffffu, s0, 2);
        s1 += __shfl_xor_sync(0xffffffffu, s1, 1);
        s1 += __shfl_xor_sync(0xffffffffu, s1, 2);
        l0 = l0 * a0 + s0;
        l1 = l1 * a1 + s1;

        // ---- O += P V (p split hi/lo in-register, v split in smem; 3 passes) ----
#pragma unroll
        for (int kj = 0; kj < 8; ++kj) {
            uint32_t aH[4], aL[4];
            split_pack(S[2 * kj][0],     S[2 * kj][1],     aH[0], aL[0]);
            split_pack(S[2 * kj][2],     S[2 * kj][3],     aH[1], aL[1]);
            split_pack(S[2 * kj + 1][0], S[2 * kj + 1][1], aH[2], aL[2]);
            split_pack(S[2 * kj + 1][2], S[2 * kj + 1][3], aH[3], aL[3]);
            int kof = kj * 16 + 2 * tq;
#pragma unroll
            for (int nd = 0; nd < 8; ++nd) {
                int col = nd * 8 + g;
                uint32_t bHf[2], bLf[2];
                bHf[0] = *(const uint32_t*)&VTH[col][kof];
                bHf[1] = *(const uint32_t*)&VTH[col][kof + 8];
                bLf[0] = *(const uint32_t*)&VTL[col][kof];
                bLf[1] = *(const uint32_t*)&VTL[col][kof + 8];
                mma16816(O[nd], aH, bHf);
                mma16816(O[nd], aH, bLf);
                mma16816(O[nd], aL, bHf);
            }
        }
        __syncthreads();   // smem K/V reuse next iter
    }

    // ---- epilogue: out = (O + band . erv) / l, write bf16-split g_att ----
    float inv0 = 1.f / l0, inv1 = 1.f / l1;
#pragma unroll
    for (int e = 0; e < 4; ++e) {
        int rl_ = rbase + ((e >> 1) << 3);
        float bnd[9];
#pragma unroll
        for (int u = 0; u < 9; ++u) bnd[u] = BAND[rl_][u];
        float inv = (e < 2) ? inv0 : inv1;
        size_t rowbase = ((size_t)(b * 1024 + i0 + rl_)) * 1024 + h * 64;
#pragma unroll
        for (int nd = 0; nd < 8; ++nd) {
            int dcol = nd * 8 + 2 * tq + (e & 1);
            float val = O[nd][e];
#pragma unroll
            for (int u = 0; u < 9; ++u) val += bnd[u] * ERVS[u * 64 + dcol];
            val *= inv;
            __nv_bfloat16 hh, ll;
            splitbf(val, hh, ll);
            g_att_hi[rowbase + dcol] = hh;
            g_att_lo[rowbase + dcol] = ll;
        }
    }
}

// --------------------------------- launch --------------------------------------
extern "C" void kernel_launch(void* const* d_in, const int* in_sizes, int n_in,
                              void* d_out, int out_size)
{
    const float* x   = (const float*)d_in[0];
    const float* c   = (const float*)d_in[1];
    const int*   msk = (const int*)  d_in[2];
    const float* Wq  = (const float*)d_in[3];
    const float* bq  = (const float*)d_in[4];
    const float* Wk  = (const float*)d_in[5];
    const float* bk  = (const float*)d_in[6];
    const float* Wv  = (const float*)d_in[7];
    const float* bv  = (const float*)d_in[8];
    const float* Wo  = (const float*)d_in[9];
    const float* bo  = (const float*)d_in[10];
    const float* erk = (const float*)d_in[11];
    const float* erv = (const float*)d_in[12];
    float* out = (float*)d_out;

    cudaFuncSetAttribute(gemm_mma, cudaFuncAttributeMaxDynamicSharedMemorySize, GEMM_SMEM);
    cudaFuncSetAttribute(attn_fused, cudaFuncAttributeMaxDynamicSharedMemorySize, ATT_SMEM);

    conv_in<<<4096, 256>>>(x, c, bq, bk, bv, bo);
    conv_w<<<dim3(32, 32, 4), 256>>>(Wq, Wk, Wv, Wo);
    gemm_mma<<<dim3(8, 16, 3), 256, GEMM_SMEM>>>(0, nullptr);   // Q,K,V
    rl_kernel<<<BHT / 8, 256>>>(erk);
    attn_fused<<<dim3(8, 32), 256, ATT_SMEM>>>(msk, erv);
    gemm_mma<<<dim3(8, 16, 1), 256, GEMM_SMEM>>>(1, out);       // @Wo + bo
}

// round 5
// speedup vs baseline: 2.4257x; 1.0576x over previous
#include <cuda_runtime.h>
#include <cuda_bf16.h>
#include <cstdint>

// Problem constants
#define B_   2
#define T_   1024
#define CH_  1024
#define H_   16
#define KC_  64
#define WIN_ 4
#define MROWS (B_ * T_)          // 2048
#define BHT  (B_ * H_ * T_)      // 32768

// ---------------- scratch (static device globals; no allocation) ----------------
__device__ float g_q[B_ * H_ * T_ * KC_];     // [B,H,T,KC], pre-scaled by 1/sqrt(KC)
__device__ float g_k[B_ * H_ * T_ * KC_];
__device__ float g_v[B_ * H_ * T_ * KC_];

// bf16 split operands for tensor-core GEMMs
__device__ __nv_bfloat16 gx_hi[MROWS * CH_];
__device__ __nv_bfloat16 gx_lo[MROWS * CH_];
__device__ __nv_bfloat16 gc_hi[MROWS * CH_];
__device__ __nv_bfloat16 gc_lo[MROWS * CH_];
__device__ __nv_bfloat16 gw_hi[4 * CH_ * CH_];   // W^T concat [q|k|v|o]: [4096][1024]
__device__ __nv_bfloat16 gw_lo[4 * CH_ * CH_];
__device__ __nv_bfloat16 g_att_hi[MROWS * CH_];  // attention out, bf16 split
__device__ __nv_bfloat16 g_att_lo[MROWS * CH_];
__device__ float g_bias[4 * CH_];                // [bq|bk|bv|bo]

// ======================= helpers ================================================
__device__ __forceinline__ void mma16816(float* c, const uint32_t* a, const uint32_t* b)
{
    asm volatile(
        "mma.sync.aligned.m16n8k16.row.col.f32.bf16.bf16.f32 "
        "{%0,%1,%2,%3}, {%4,%5,%6,%7}, {%8,%9}, {%0,%1,%2,%3};"
        : "+f"(c[0]), "+f"(c[1]), "+f"(c[2]), "+f"(c[3])
        : "r"(a[0]), "r"(a[1]), "r"(a[2]), "r"(a[3]), "r"(b[0]), "r"(b[1]));
}

__device__ __forceinline__ void splitbf(float x, __nv_bfloat16& h, __nv_bfloat16& l)
{
    h = __float2bfloat16_rn(x);
    l = __float2bfloat16_rn(x - __bfloat162float(h));
}

__device__ __forceinline__ void split_pack(float x, float y, uint32_t& hi, uint32_t& lo)
{
    __nv_bfloat16 hx, lx, hy, ly;
    splitbf(x, hx, lx); splitbf(y, hy, ly);
    __nv_bfloat162 th = __halves2bfloat162(hx, hy);
    __nv_bfloat162 tl = __halves2bfloat162(lx, ly);
    hi = *reinterpret_cast<uint32_t*>(&th);
    lo = *reinterpret_cast<uint32_t*>(&tl);
}

__device__ __forceinline__ uint32_t smem_u32(const void* p) {
    uint32_t a;
    asm("{ .reg .u64 t; cvta.to.shared.u64 t, %1; cvt.u32.u64 %0, t; }"
        : "=r"(a) : "l"(p));
    return a;
}

__device__ __forceinline__ void cpa16(uint32_t dst, const void* src) {
    asm volatile("cp.async.cg.shared.global [%0], [%1], 16;" :: "r"(dst), "l"(src));
}

// ======================= conversion kernels ====================================
__global__ __launch_bounds__(256) void conv_in(
    const float* __restrict__ x, const float* __restrict__ c,
    const float* __restrict__ bq, const float* __restrict__ bk,
    const float* __restrict__ bv, const float* __restrict__ bo)
{
    int i = blockIdx.x * 256 + threadIdx.x;   // float4 index, 0..1048575
    const float4* src;
    __nv_bfloat162 *dh, *dl;
    int j;
    if (i < 524288) {
        src = (const float4*)x; j = i;
        dh = (__nv_bfloat162*)gx_hi; dl = (__nv_bfloat162*)gx_lo;
    } else {
        src = (const float4*)c; j = i - 524288;
        dh = (__nv_bfloat162*)gc_hi; dl = (__nv_bfloat162*)gc_lo;
    }
    float4 v = src[j];
    __nv_bfloat16 hx, lx, hy, ly, hz, lz, hw, lw;
    splitbf(v.x, hx, lx); splitbf(v.y, hy, ly);
    splitbf(v.z, hz, lz); splitbf(v.w, hw, lw);
    dh[2 * j]     = __halves2bfloat162(hx, hy);
    dh[2 * j + 1] = __halves2bfloat162(hz, hw);
    dl[2 * j]     = __halves2bfloat162(lx, ly);
    dl[2 * j + 1] = __halves2bfloat162(lz, lw);
    if (i < 4096) {
        float b = (i < 1024) ? bq[i] : (i < 2048) ? bk[i - 1024]
                : (i < 3072) ? bv[i - 2048] : bo[i - 3072];
        g_bias[i] = b;
    }
}

__global__ __launch_bounds__(256) void conv_w(
    const float* __restrict__ Wq, const float* __restrict__ Wk,
    const float* __restrict__ Wv, const float* __restrict__ Wo)
{
    __shared__ float tile[32][33];
    int z = blockIdx.z;
    const float* W = (z == 0) ? Wq : (z == 1) ? Wk : (z == 2) ? Wv : Wo;
    int n0 = blockIdx.x * 32, k0 = blockIdx.y * 32;
    int tx = threadIdx.x & 31, ty = threadIdx.x >> 5;
#pragma unroll
    for (int u = 0; u < 4; ++u) {
        int k = k0 + ty + u * 8;
        tile[ty + u * 8][tx] = W[k * 1024 + n0 + tx];
    }
    __syncthreads();
#pragma unroll
    for (int u = 0; u < 4; ++u) {
        int r = ty + u * 8;
        float v = tile[tx][r];               // = W[k0+tx][n0+r]
        int dst = (z * 1024 + n0 + r) * 1024 + k0 + tx;
        __nv_bfloat16 h, l;
        splitbf(v, h, l);
        gw_hi[dst] = h;
        gw_lo[dst] = l;
    }
}

// ======================= cp.async double-buffered bf16-split GEMM ==============
#define LDK 72                        // padded k-stride (bf16 elems), 144B rows
#define TILE_B (128 * LDK * 2)        // one [128][LDK] bf16 tile = 18432 B
#define STAGE_B (4 * TILE_B)          // Ah,Al,Bh,Bl = 73728 B
#define GEMM_SMEM (2 * STAGE_B)       // 147456 B
__global__ __launch_bounds__(256) void gemm_mma(int mode, float* __restrict__ finalout)
{
    extern __shared__ __nv_bfloat16 sm[];
    uint32_t sbase = smem_u32(sm);

    int tid = threadIdx.x;
    int wid = tid >> 5, lane = tid & 31;
    int g = lane >> 2, tg = lane & 3;
    int warp_m = wid & 1, warp_n = wid >> 1;
    int z = (mode == 0) ? (int)blockIdx.z : 3;

    const __nv_bfloat16 *A_hi, *A_lo;
    if (mode == 0) {
        if (z == 0) { A_hi = gx_hi; A_lo = gx_lo; }
        else        { A_hi = gc_hi; A_lo = gc_lo; }
    } else { A_hi = g_att_hi; A_lo = g_att_lo; }
    int arow0 = blockIdx.y * 128;
    int brow0 = z * 1024 + blockIdx.x * 128;

    // async stage issuer: 4 tiles x 128 rows x 128B, 16B chunks
    auto issue_stage = [&](int stage, int k0) {
        const __nv_bfloat16* srcs[4] = {A_hi, A_lo, gw_hi, gw_lo};
        int rows0[4] = {arow0, arow0, brow0, brow0};
        uint32_t stoff = sbase + (uint32_t)stage * STAGE_B;
#pragma unroll
        for (int arr = 0; arr < 4; ++arr) {
#pragma unroll
            for (int u = 0; u < 4; ++u) {
                int lin = tid + u * 256;          // 0..1023
                int r = lin >> 3, c8 = lin & 7;
                cpa16(stoff + (uint32_t)arr * TILE_B + r * 144 + c8 * 16,
                      srcs[arr] + (size_t)(rows0[arr] + r) * 1024 + k0 + c8 * 8);
            }
        }
        asm volatile("cp.async.commit_group;" ::: "memory");
    };

    float acc[4][4][4];
#pragma unroll
    for (int mi = 0; mi < 4; ++mi)
#pragma unroll
        for (int ni = 0; ni < 4; ++ni)
#pragma unroll
            for (int e = 0; e < 4; ++e) acc[mi][ni][e] = 0.f;

    issue_stage(0, 0);

    for (int s = 0; s < 16; ++s) {
        asm volatile("cp.async.wait_group 0;" ::: "memory");
        __syncthreads();
        if (s + 1 < 16) issue_stage((s + 1) & 1, (s + 1) * 64);

        int st = s & 1;
        const __nv_bfloat16 (*Ah)[LDK] = (const __nv_bfloat16(*)[LDK])(sm + st * (STAGE_B / 2));
        const __nv_bfloat16 (*Al)[LDK] = (const __nv_bfloat16(*)[LDK])(sm + st * (STAGE_B / 2) + TILE_B / 2);
        const __nv_bfloat16 (*Bh)[LDK] = (const __nv_bfloat16(*)[LDK])(sm + st * (STAGE_B / 2) + 2 * (TILE_B / 2));
        const __nv_bfloat16 (*Bl)[LDK] = (const __nv_bfloat16(*)[LDK])(sm + st * (STAGE_B / 2) + 3 * (TILE_B / 2));

#pragma unroll
        for (int kk = 0; kk < 4; ++kk) {
            int kof = kk * 16 + 2 * tg;
            uint32_t ah[4][4], al[4][4], bh[4][2], bl[4][2];
#pragma unroll
            for (int mi = 0; mi < 4; ++mi) {
                int row = warp_m * 64 + mi * 16 + g;
                ah[mi][0] = *(const uint32_t*)&Ah[row][kof];
                ah[mi][1] = *(const uint32_t*)&Ah[row + 8][kof];
                ah[mi][2] = *(const uint32_t*)&Ah[row][kof + 8];
                ah[mi][3] = *(const uint32_t*)&Ah[row + 8][kof + 8];
                al[mi][0] = *(const uint32_t*)&Al[row][kof];
                al[mi][1] = *(const uint32_t*)&Al[row + 8][kof];
                al[mi][2] = *(const uint32_t*)&Al[row][kof + 8];
                al[mi][3] = *(const uint32_t*)&Al[row + 8][kof + 8];
            }
#pragma unroll
            for (int ni = 0; ni < 4; ++ni) {
                int col = warp_n * 32 + ni * 8 + g;
                bh[ni][0] = *(const uint32_t*)&Bh[col][kof];
                bh[ni][1] = *(const uint32_t*)&Bh[col][kof + 8];
                bl[ni][0] = *(const uint32_t*)&Bl[col][kof];
                bl[ni][1] = *(const uint32_t*)&Bl[col][kof + 8];
            }
#pragma unroll
            for (int mi = 0; mi < 4; ++mi)
#pragma unroll
                for (int ni = 0; ni < 4; ++ni) {
                    mma16816(acc[mi][ni], ah[mi], bh[ni]);
                    mma16816(acc[mi][ni], ah[mi], bl[ni]);
                    mma16816(acc[mi][ni], al[mi], bh[ni]);
                }
        }
        __syncthreads();
    }

    float scale = (mode == 0 && z == 0) ? 0.125f : 1.0f;
    float* dstg = (mode == 1) ? finalout : (z == 0) ? g_q : (z == 1) ? g_k : g_v;
#pragma unroll
    for (int mi = 0; mi < 4; ++mi) {
#pragma unroll
        for (int ni = 0; ni < 4; ++ni) {
#pragma unroll
            for (int e = 0; e < 4; ++e) {
                int row = blockIdx.y * 128 + warp_m * 64 + mi * 16 + g + ((e >> 1) ? 8 : 0);
                int col = blockIdx.x * 128 + warp_n * 32 + ni * 8 + 2 * tg + (e & 1);
                float v = (acc[mi][ni][e] + g_bias[z * 1024 + col]) * scale;
                if (mode == 0) {
                    int h = col >> 6, bb = row >> 10, t = row & 1023, d = col & 63;
                    dstg[(((bb * 16 + h) << 16) | (t << 6)) + d] = v;
                } else {
                    dstg[(size_t)row * 1024 + col] = v;
                }
            }
        }
    }
}

// =================== fused flash attention (rl + scores+softmax+pv+bands) ======
// grid (8 i-tiles, 32 bh), 256 threads. Smem layout (bytes):
//   QH 0, QL 18432, KH 36864, KL 55296  : [128][72] bf16 each
//   VTH 73728, VTL 91136                : [64][136] bf16 each (v transposed)
//   BAND 108544 : [128][12] f32, RLS 114688 : [128][9] f32,
//   ERVS 119296 : 576 f32, ERKS 121600 : 576 f32
#define ATT_SMEM 123904
__global__ __launch_bounds__(256, 1) void attn_fused(
    const int* __restrict__ mask, const float* __restrict__ erv,
    const float* __restrict__ erk)
{
    extern __shared__ char smc[];
    __nv_bfloat16 (*QH)[72]  = (__nv_bfloat16(*)[72])(smc);
    __nv_bfloat16 (*QL)[72]  = (__nv_bfloat16(*)[72])(smc + 18432);
    __nv_bfloat16 (*KH)[72]  = (__nv_bfloat16(*)[72])(smc + 36864);
    __nv_bfloat16 (*KL)[72]  = (__nv_bfloat16(*)[72])(smc + 55296);
    __nv_bfloat16 (*VTH)[136] = (__nv_bfloat16(*)[136])(smc + 73728);
    __nv_bfloat16 (*VTL)[136] = (__nv_bfloat16(*)[136])(smc + 91136);
    float (*BAND)[12] = (float(*)[12])(smc + 108544);
    float (*RLS)[9]   = (float(*)[9])(smc + 114688);
    float* ERVS       = (float*)(smc + 119296);
    float* ERKS       = (float*)(smc + 121600);

    int tid = threadIdx.x, wid = tid >> 5, lane = tid & 31;
    int g = lane >> 2, tq = lane & 3;
    int bh = blockIdx.y, b = bh >> 4, h = bh & 15;
    int i0 = blockIdx.x * 128;

    // ---- load Q tile (fp32 -> hi/lo bf16), ERKS/ERVS, zero BAND ----
    {
        const float4* qsrc = (const float4*)(g_q + ((size_t)bh * 1024 + i0) * 64);
        for (int idx = tid; idx < 2048; idx += 256) {
            int r = idx >> 4, c4 = (idx & 15) * 4;
            float4 v = qsrc[idx];
            __nv_bfloat16 hh, ll;
            splitbf(v.x, hh, ll); QH[r][c4] = hh;     QL[r][c4] = ll;
            splitbf(v.y, hh, ll); QH[r][c4 + 1] = hh; QL[r][c4 + 1] = ll;
            splitbf(v.z, hh, ll); QH[r][c4 + 2] = hh; QL[r][c4 + 2] = ll;
            splitbf(v.w, hh, ll); QH[r][c4 + 3] = hh; QL[r][c4 + 3] = ll;
        }
        for (int idx = tid; idx < 576; idx += 256) { ERVS[idx] = erv[idx]; ERKS[idx] = erk[idx]; }
        for (int idx = tid; idx < 128 * 12; idx += 256) ((float*)BAND)[idx] = 0.f;
    }
    __syncthreads();

    // ---- rel-k logits from resident Q tile: RLS[r][u] = q_r . erk_u ----
    for (int idx = tid; idx < 1152; idx += 256) {
        int r = idx / 9, u = idx - r * 9;
        float s = 0.f;
        const float* e = ERKS + u * 64;
#pragma unroll
        for (int d = 0; d < 64; ++d)
            s += (__bfloat162float(QH[r][d]) + __bfloat162float(QL[r][d])) * e[d];
        RLS[r][u] = s;
    }

    float O[8][4];
#pragma unroll
    for (int nd = 0; nd < 8; ++nd)
#pragma unroll
        for (int e = 0; e < 4; ++e) O[nd][e] = 0.f;
    float m0 = -1e30f, m1 = -1e30f, l0 = 0.f, l1 = 0.f;

    const int rbase = wid * 16 + g;

    for (int jt = 0; jt < 8; ++jt) {
        int j0 = jt * 128;
        if (jt > 0) __syncthreads();   // protect K/V smem reuse
        // ---- fill K (hi/lo) and V^T (hi/lo) ----
        const float4* ksrc = (const float4*)(g_k + ((size_t)bh * 1024 + j0) * 64);
        for (int idx = tid; idx < 2048; idx += 256) {
            int r = idx >> 4, c4 = (idx & 15) * 4;
            float4 v = ksrc[idx];
            __nv_bfloat16 hh, ll;
            splitbf(v.x, hh, ll); KH[r][c4] = hh;     KL[r][c4] = ll;
            splitbf(v.y, hh, ll); KH[r][c4 + 1] = hh; KL[r][c4 + 1] = ll;
            splitbf(v.z, hh, ll); KH[r][c4 + 2] = hh; KL[r][c4 + 2] = ll;
            splitbf(v.w, hh, ll); KH[r][c4 + 3] = hh; KL[r][c4 + 3] = ll;
        }
        {
            int jj = tid >> 1, halfc = tid & 1;
            const float4* vsrc = (const float4*)(g_v + ((size_t)bh * 1024 + j0 + jj) * 64 + halfc * 32);
#pragma unroll
            for (int u = 0; u < 8; ++u) {
                float4 v = vsrc[u];
                int d0 = halfc * 32 + u * 4;
                __nv_bfloat16 hh, ll;
                splitbf(v.x, hh, ll); VTH[d0][jj] = hh;     VTL[d0][jj] = ll;
                splitbf(v.y, hh, ll); VTH[d0 + 1][jj] = hh; VTL[d0 + 1][jj] = ll;
                splitbf(v.z, hh, ll); VTH[d0 + 2][jj] = hh; VTL[d0 + 2][jj] = ll;
                splitbf(v.w, hh, ll); VTH[d0 + 3][jj] = hh; VTL[d0 + 3][jj] = ll;
            }
        }
        __syncthreads();

        // ---- S = Qs K^T (bf16 split, 3 passes) ----
        float S[16][4];
#pragma unroll
        for (int nf = 0; nf < 16; ++nf)
#pragma unroll
            for (int e = 0; e < 4; ++e) S[nf][e] = 0.f;
#pragma unroll
        for (int ks = 0; ks < 4; ++ks) {
            int kof = ks * 16 + 2 * tq;
            uint32_t ah[4], al[4];
            ah[0] = *(const uint32_t*)&QH[rbase][kof];
            ah[1] = *(const uint32_t*)&QH[rbase + 8][kof];
            ah[2] = *(const uint32_t*)&QH[rbase][kof + 8];
            ah[3] = *(const uint32_t*)&QH[rbase + 8][kof + 8];
            al[0] = *(const uint32_t*)&QL[rbase][kof];
            al[1] = *(const uint32_t*)&QL[rbase + 8][kof];
            al[2] = *(const uint32_t*)&QL[rbase][kof + 8];
            al[3] = *(const uint32_t*)&QL[rbase + 8][kof + 8];
#pragma unroll
            for (int nf = 0; nf < 16; ++nf) {
                int col = nf * 8 + g;
                uint32_t bhf[2], blf[2];
                bhf[0] = *(const uint32_t*)&KH[col][kof];
                bhf[1] = *(const uint32_t*)&KH[col][kof + 8];
                blf[0] = *(const uint32_t*)&KL[col][kof];
                blf[1] = *(const uint32_t*)&KL[col][kof + 8];
                mma16816(S[nf], ah, bhf);
                mma16816(S[nf], ah, blf);
                mma16816(S[nf], al, bhf);
            }
        }

        // ---- fixup: rel-k band + mask; row max ----
        float mx0 = -1e30f, mx1 = -1e30f;
        const int* mrow0 = mask + (((size_t)b << 10) + i0 + rbase) * 1024 + j0;
        const int* mrow1 = mrow0 + (size_t)8 * 1024;
#pragma unroll
        for (int nf = 0; nf < 16; ++nf) {
#pragma unroll
            for (int e = 0; e < 4; ++e) {
                int rl_ = rbase + ((e >> 1) << 3);
                int jloc = nf * 8 + 2 * tq + (e & 1);
                float s = S[nf][e];
                int d = (j0 + jloc) - (i0 + rl_);
                if ((unsigned)(d + 4) <= 8u) s += RLS[rl_][d + 4];
                int mv = (e < 2) ? mrow0[jloc] : mrow1[jloc];
                if (mv == 0) s = 1e-4f;
                S[nf][e] = s;
                if (e < 2) mx0 = fmaxf(mx0, s); else mx1 = fmaxf(mx1, s);
            }
        }
        mx0 = fmaxf(mx0, __shfl_xor_sync(0xffffffffu, mx0, 1));
        mx0 = fmaxf(mx0, __shfl_xor_sync(0xffffffffu, mx0, 2));
        mx1 = fmaxf(mx1, __shfl_xor_sync(0xffffffffu, mx1, 1));
        mx1 = fmaxf(mx1, __shfl_xor_sync(0xffffffffu, mx1, 2));
        float mn0 = fmaxf(m0, mx0), mn1 = fmaxf(m1, mx1);
        float a0 = __expf(m0 - mn0), a1 = __expf(m1 - mn1);
        m0 = mn0; m1 = mn1;

        // rescale output acc + band
#pragma unroll
        for (int nd = 0; nd < 8; ++nd) {
            O[nd][0] *= a0; O[nd][1] *= a0; O[nd][2] *= a1; O[nd][3] *= a1;
        }
        if (tq == 0) {
#pragma unroll
            for (int u = 0; u < 9; ++u) {
                BAND[rbase][u] *= a0;
                BAND[rbase + 8][u] *= a1;
            }
        }
        __syncwarp();

        // ---- p = exp(s - m), row sums, band adds ----
        float s0 = 0.f, s1 = 0.f;
#pragma unroll
        for (int nf = 0; nf < 16; ++nf) {
#pragma unroll
            for (int e = 0; e < 4; ++e) {
                float p = __expf(S[nf][e] - ((e < 2) ? mn0 : mn1));
                S[nf][e] = p;
                if (e < 2) s0 += p; else s1 += p;
                int rl_ = rbase + ((e >> 1) << 3);
                int d = (j0 + nf * 8 + 2 * tq + (e & 1)) - (i0 + rl_);
                if ((unsigned)(d + 4) <= 8u) BAND[rl_][d + 4] += p;
            }
        }
        s0 += __shfl_xor_sync(0xffffffffu, s0, 1);
        s0 += __shfl_xor_sync(0xffffffffu, s0, 2);
        s1 += __shfl_xor_sync(0xffffffffu, s1, 1);
        s1 += __shfl_xor_sync(0xffffffffu, s1, 2);
        l0 = l0 * a0 + s0;
        l1 = l1 * a1 + s1;

        // ---- O += P V (p split hi/lo in-register, v split in smem; 3 passes) ----
#pragma unroll
        for (int kj = 0; kj < 8; ++kj) {
            uint32_t aH[4], aL[4];
            split_pack(S[2 * kj][0],     S[2 * kj][1],     aH[0], aL[0]);
            split_pack(S[2 * kj][2],     S[2 * kj][3],     aH[1], aL[1]);
            split_pack(S[2 * kj + 1][0], S[2 * kj + 1][1], aH[2], aL[2]);
            split_pack(S[2 * kj + 1][2], S[2 * kj + 1][3], aH[3], aL[3]);
            int kof = kj * 16 + 2 * tq;
#pragma unroll
            for (int nd = 0; nd < 8; ++nd) {
                int col = nd * 8 + g;
                uint32_t bHf[2], bLf[2];
                bHf[0] = *(const uint32_t*)&VTH[col][kof];
                bHf[1] = *(const uint32_t*)&VTH[col][kof + 8];
                bLf[0] = *(const uint32_t*)&VTL[col][kof];
                bLf[1] = *(const uint32_t*)&VTL[col][kof + 8];
                mma16816(O[nd], aH, bHf);
                mma16816(O[nd], aH, bLf);
                mma16816(O[nd], aL, bHf);
            }
        }
    }

    // ---- epilogue: out = (O + band . erv) / l, write bf16-split g_att ----
    float inv0 = 1.f / l0, inv1 = 1.f / l1;
#pragma unroll
    for (int e = 0; e < 4; ++e) {
        int rl_ = rbase + ((e >> 1) << 3);
        float bnd[9];
#pragma unroll
        for (int u = 0; u < 9; ++u) bnd[u] = BAND[rl_][u];
        float inv = (e < 2) ? inv0 : inv1;
        size_t rowbase = ((size_t)(b * 1024 + i0 + rl_)) * 1024 + h * 64;
#pragma unroll
        for (int nd = 0; nd < 8; ++nd) {
            int dcol = nd * 8 + 2 * tq + (e & 1);
            float val = O[nd][e];
#pragma unroll
            for (int u = 0; u < 9; ++u) val += bnd[u] * ERVS[u * 64 + dcol];
            val *= inv;
            __nv_bfloat16 hh, ll;
            splitbf(val, hh, ll);
            g_att_hi[rowbase + dcol] = hh;
            g_att_lo[rowbase + dcol] = ll;
        }
    }
}

// --------------------------------- launch --------------------------------------
extern "C" void kernel_launch(void* const* d_in, const int* in_sizes, int n_in,
                              void* d_out, int out_size)
{
    const float* x   = (const float*)d_in[0];
    const float* c   = (const float*)d_in[1];
    const int*   msk = (const int*)  d_in[2];
    const float* Wq  = (const float*)d_in[3];
    const float* bq  = (const float*)d_in[4];
    const float* Wk  = (const float*)d_in[5];
    const float* bk  = (const float*)d_in[6];
    const float* Wv  = (const float*)d_in[7];
    const float* bv  = (const float*)d_in[8];
    const float* Wo  = (const float*)d_in[9];
    const float* bo  = (const float*)d_in[10];
    const float* erk = (const float*)d_in[11];
    const float* erv = (const float*)d_in[12];
    float* out = (float*)d_out;

    cudaFuncSetAttribute(gemm_mma, cudaFuncAttributeMaxDynamicSharedMemorySize, GEMM_SMEM);
    cudaFuncSetAttribute(attn_fused, cudaFuncAttributeMaxDynamicSharedMemorySize, ATT_SMEM);

    conv_in<<<4096, 256>>>(x, c, bq, bk, bv, bo);
    conv_w<<<dim3(32, 32, 4), 256>>>(Wq, Wk, Wv, Wo);
    gemm_mma<<<dim3(8, 16, 3), 256, GEMM_SMEM>>>(0, nullptr);   // Q,K,V
    attn_fused<<<dim3(8, 32), 256, ATT_SMEM>>>(msk, erv, erk);
    gemm_mma<<<dim3(8, 16, 1), 256, GEMM_SMEM>>>(1, out);       // @Wo + bo
}

// round 7
// speedup vs baseline: 2.5456x; 1.0494x over previous
#include <cuda_runtime.h>
#include <cuda_bf16.h>
#include <cstdint>

// Problem constants
#define B_   2
#define T_   1024
#define CH_  1024
#define H_   16
#define KC_  64
#define WIN_ 4
#define MROWS (B_ * T_)          // 2048
#define BHT  (B_ * H_ * T_)      // 32768

// ---------------- scratch (static device globals; no allocation) ----------------
// q/k/v pre-split bf16 hi/lo in [B,H,T,KC] layout (q pre-scaled by 1/sqrt(KC))
__device__ __nv_bfloat16 g_q_hi[BHT * KC_];
__device__ __nv_bfloat16 g_q_lo[BHT * KC_];
__device__ __nv_bfloat16 g_k_hi[BHT * KC_];
__device__ __nv_bfloat16 g_k_lo[BHT * KC_];
__device__ __nv_bfloat16 g_v_hi[BHT * KC_];
__device__ __nv_bfloat16 g_v_lo[BHT * KC_];

// bf16 split operands for tensor-core GEMMs
__device__ __nv_bfloat16 gx_hi[MROWS * CH_];
__device__ __nv_bfloat16 gx_lo[MROWS * CH_];
__device__ __nv_bfloat16 gc_hi[MROWS * CH_];
__device__ __nv_bfloat16 gc_lo[MROWS * CH_];
__device__ __nv_bfloat16 gw_hi[4 * CH_ * CH_];   // W^T concat [q|k|v|o]: [4096][1024]
__device__ __nv_bfloat16 gw_lo[4 * CH_ * CH_];
__device__ __nv_bfloat16 g_att_hi[MROWS * CH_];  // attention out, bf16 split
__device__ __nv_bfloat16 g_att_lo[MROWS * CH_];
__device__ float g_bias[4 * CH_];                // [bq|bk|bv|bo]
__device__ uint32_t g_mbits[MROWS * (T_ / 32)];  // bit-packed mask [B*T][32]

// ======================= helpers ================================================
__device__ __forceinline__ void mma16816(float* c, const uint32_t* a, const uint32_t* b)
{
    asm volatile(
        "mma.sync.aligned.m16n8k16.row.col.f32.bf16.bf16.f32 "
        "{%0,%1,%2,%3}, {%4,%5,%6,%7}, {%8,%9}, {%0,%1,%2,%3};"
        : "+f"(c[0]), "+f"(c[1]), "+f"(c[2]), "+f"(c[3])
        : "r"(a[0]), "r"(a[1]), "r"(a[2]), "r"(a[3]), "r"(b[0]), "r"(b[1]));
}

__device__ __forceinline__ void splitbf(float x, __nv_bfloat16& h, __nv_bfloat16& l)
{
    h = __float2bfloat16_rn(x);
    l = __float2bfloat16_rn(x - __bfloat162float(h));
}

__device__ __forceinline__ void split_pack(float x, float y, uint32_t& hi, uint32_t& lo)
{
    __nv_bfloat16 hx, lx, hy, ly;
    splitbf(x, hx, lx); splitbf(y, hy, ly);
    __nv_bfloat162 th = __halves2bfloat162(hx, hy);
    __nv_bfloat162 tl = __halves2bfloat162(lx, ly);
    hi = *reinterpret_cast<uint32_t*>(&th);
    lo = *reinterpret_cast<uint32_t*>(&tl);
}

__device__ __forceinline__ uint32_t smem_u32(const void* p) {
    uint32_t a;
    asm("{ .reg .u64 t; cvta.to.shared.u64 t, %1; cvt.u32.u64 %0, t; }"
        : "=r"(a) : "l"(p));
    return a;
}

__device__ __forceinline__ void cpa16(uint32_t dst, const void* src) {
    asm volatile("cp.async.cg.shared.global [%0], [%1], 16;" :: "r"(dst), "l"(src));
}

// ======================= prep kernels ==========================================
__global__ __launch_bounds__(256) void conv_in(
    const float* __restrict__ x, const float* __restrict__ c,
    const float* __restrict__ bq, const float* __restrict__ bk,
    const float* __restrict__ bv, const float* __restrict__ bo)
{
    int i = blockIdx.x * 256 + threadIdx.x;   // float4 index
    const float4* src;
    __nv_bfloat162 *dh, *dl;
    int j;
    if (i < 524288) {
        src = (const float4*)x; j = i;
        dh = (__nv_bfloat162*)gx_hi; dl = (__nv_bfloat162*)gx_lo;
    } else {
        src = (const float4*)c; j = i - 524288;
        dh = (__nv_bfloat162*)gc_hi; dl = (__nv_bfloat162*)gc_lo;
    }
    float4 v = src[j];
    __nv_bfloat16 hx, lx, hy, ly, hz, lz, hw, lw;
    splitbf(v.x, hx, lx); splitbf(v.y, hy, ly);
    splitbf(v.z, hz, lz); splitbf(v.w, hw, lw);
    dh[2 * j]     = __halves2bfloat162(hx, hy);
    dh[2 * j + 1] = __halves2bfloat162(hz, hw);
    dl[2 * j]     = __halves2bfloat162(lx, ly);
    dl[2 * j + 1] = __halves2bfloat162(lz, lw);
    if (i < 4096) {
        float b = (i < 1024) ? bq[i] : (i < 2048) ? bk[i - 1024]
                : (i < 3072) ? bv[i - 2048] : bo[i - 3072];
        g_bias[i] = b;
    }
}

__global__ __launch_bounds__(256) void conv_w(
    const float* __restrict__ Wq, const float* __restrict__ Wk,
    const float* __restrict__ Wv, const float* __restrict__ Wo)
{
    __shared__ float tile[32][33];
    int z = blockIdx.z;
    const float* W = (z == 0) ? Wq : (z == 1) ? Wk : (z == 2) ? Wv : Wo;
    int n0 = blockIdx.x * 32, k0 = blockIdx.y * 32;
    int tx = threadIdx.x & 31, ty = threadIdx.x >> 5;
#pragma unroll
    for (int u = 0; u < 4; ++u) {
        int k = k0 + ty + u * 8;
        tile[ty + u * 8][tx] = W[k * 1024 + n0 + tx];
    }
    __syncthreads();
#pragma unroll
    for (int u = 0; u < 4; ++u) {
        int r = ty + u * 8;
        float v = tile[tx][r];               // = W[k0+tx][n0+r]
        int dst = (z * 1024 + n0 + r) * 1024 + k0 + tx;
        __nv_bfloat16 h, l;
        splitbf(v, h, l);
        gw_hi[dst] = h;
        gw_lo[dst] = l;
    }
}

__global__ __launch_bounds__(256) void mask_pack(const int* __restrict__ mask)
{
    int idx = blockIdx.x * 256 + threadIdx.x;     // 0 .. 2M-1
    uint32_t bits = __ballot_sync(0xffffffffu, mask[idx] != 0);
    if ((threadIdx.x & 31) == 0) g_mbits[idx >> 5] = bits;
}

// ======================= cp.async double-buffered bf16-split GEMM ==============
#define LDK 72                        // padded k-stride (bf16 elems), 144B rows
#define TILE_B (128 * LDK * 2)        // one [128][LDK] bf16 tile = 18432 B
#define STAGE_B (4 * TILE_B)          // Ah,Al,Bh,Bl = 73728 B
#define GEMM_SMEM (2 * STAGE_B)       // 147456 B
__global__ __launch_bounds__(256) void gemm_mma(int mode, float* __restrict__ finalout)
{
    extern __shared__ __nv_bfloat16 sm[];
    uint32_t sbase = smem_u32(sm);

    int tid = threadIdx.x;
    int wid = tid >> 5, lane = tid & 31;
    int g = lane >> 2, tg = lane & 3;
    int warp_m = wid & 1, warp_n = wid >> 1;
    int z = (mode == 0) ? (int)blockIdx.z : 3;

    const __nv_bfloat16 *A_hi, *A_lo;
    if (mode == 0) {
        if (z == 0) { A_hi = gx_hi; A_lo = gx_lo; }
        else        { A_hi = gc_hi; A_lo = gc_lo; }
    } else { A_hi = g_att_hi; A_lo = g_att_lo; }
    int arow0 = blockIdx.y * 128;
    int brow0 = z * 1024 + blockIdx.x * 128;

    auto issue_stage = [&](int stage, int k0) {
        const __nv_bfloat16* srcs[4] = {A_hi, A_lo, gw_hi, gw_lo};
        int rows0[4] = {arow0, arow0, brow0, brow0};
        uint32_t stoff = sbase + (uint32_t)stage * STAGE_B;
#pragma unroll
        for (int arr = 0; arr < 4; ++arr) {
#pragma unroll
            for (int u = 0; u < 4; ++u) {
                int lin = tid + u * 256;
                int r = lin >> 3, c8 = lin & 7;
                cpa16(stoff + (uint32_t)arr * TILE_B + r * 144 + c8 * 16,
                      srcs[arr] + (size_t)(rows0[arr] + r) * 1024 + k0 + c8 * 8);
            }
        }
        asm volatile("cp.async.commit_group;" ::: "memory");
    };

    float acc[4][4][4];
#pragma unroll
    for (int mi = 0; mi < 4; ++mi)
#pragma unroll
        for (int ni = 0; ni < 4; ++ni)
#pragma unroll
            for (int e = 0; e < 4; ++e) acc[mi][ni][e] = 0.f;

    issue_stage(0, 0);

    for (int s = 0; s < 16; ++s) {
        asm volatile("cp.async.wait_group 0;" ::: "memory");
        __syncthreads();
        if (s + 1 < 16) issue_stage((s + 1) & 1, (s + 1) * 64);

        int st = s & 1;
        const __nv_bfloat16 (*Ah)[LDK] = (const __nv_bfloat16(*)[LDK])(sm + st * (STAGE_B / 2));
        const __nv_bfloat16 (*Al)[LDK] = (const __nv_bfloat16(*)[LDK])(sm + st * (STAGE_B / 2) + TILE_B / 2);
        const __nv_bfloat16 (*Bh)[LDK] = (const __nv_bfloat16(*)[LDK])(sm + st * (STAGE_B / 2) + 2 * (TILE_B / 2));
        const __nv_bfloat16 (*Bl)[LDK] = (const __nv_bfloat16(*)[LDK])(sm + st * (STAGE_B / 2) + 3 * (TILE_B / 2));

#pragma unroll
        for (int kk = 0; kk < 4; ++kk) {
            int kof = kk * 16 + 2 * tg;
            uint32_t ah[4][4], al[4][4], bh[4][2], bl[4][2];
#pragma unroll
            for (int mi = 0; mi < 4; ++mi) {
                int row = warp_m * 64 + mi * 16 + g;
                ah[mi][0] = *(const uint32_t*)&Ah[row][kof];
                ah[mi][1] = *(const uint32_t*)&Ah[row + 8][kof];
                ah[mi][2] = *(const uint32_t*)&Ah[row][kof + 8];
                ah[mi][3] = *(const uint32_t*)&Ah[row + 8][kof + 8];
                al[mi][0] = *(const uint32_t*)&Al[row][kof];
                al[mi][1] = *(const uint32_t*)&Al[row + 8][kof];
                al[mi][2] = *(const uint32_t*)&Al[row][kof + 8];
                al[mi][3] = *(const uint32_t*)&Al[row + 8][kof + 8];
            }
#pragma unroll
            for (int ni = 0; ni < 4; ++ni) {
                int col = warp_n * 32 + ni * 8 + g;
                bh[ni][0] = *(const uint32_t*)&Bh[col][kof];
                bh[ni][1] = *(const uint32_t*)&Bh[col][kof + 8];
                bl[ni][0] = *(const uint32_t*)&Bl[col][kof];
                bl[ni][1] = *(const uint32_t*)&Bl[col][kof + 8];
            }
#pragma unroll
            for (int mi = 0; mi < 4; ++mi)
#pragma unroll
                for (int ni = 0; ni < 4; ++ni) {
                    mma16816(acc[mi][ni], ah[mi], bh[ni]);
                    mma16816(acc[mi][ni], ah[mi], bl[ni]);
                    mma16816(acc[mi][ni], al[mi], bh[ni]);
                }
        }
        __syncthreads();
    }

    float scale = (mode == 0 && z == 0) ? 0.125f : 1.0f;
    __nv_bfloat16* dsth = (z == 0) ? g_q_hi : (z == 1) ? g_k_hi : g_v_hi;
    __nv_bfloat16* dstl = (z == 0) ? g_q_lo : (z == 1) ? g_k_lo : g_v_lo;
#pragma unroll
    for (int mi = 0; mi < 4; ++mi) {
#pragma unroll
        for (int ni = 0; ni < 4; ++ni) {
#pragma unroll
            for (int e = 0; e < 4; ++e) {
                int row = blockIdx.y * 128 + warp_m * 64 + mi * 16 + g + ((e >> 1) ? 8 : 0);
                int col = blockIdx.x * 128 + warp_n * 32 + ni * 8 + 2 * tg + (e & 1);
                float v = (acc[mi][ni][e] + g_bias[z * 1024 + col]) * scale;
                if (mode == 0) {
                    int h = col >> 6, bb = row >> 10, t = row & 1023, d = col & 63;
                    int idx = (((bb * 16 + h) << 16) | (t << 6)) + d;
                    __nv_bfloat16 hh, ll;
                    splitbf(v, hh, ll);
                    dsth[idx] = hh;
                    dstl[idx] = ll;
                } else {
                    finalout[(size_t)row * 1024 + col] = v;
                }
            }
        }
    }
}

// =================== fused flash attention ======================================
// grid (8 i-tiles, 32 bh), 256 threads, 2 CTAs/SM. i-tile=128, j-tile=64.
// Smem (bytes):
//   QH 0, QL 18432                  : [128][72] bf16
//   KH 36864, KL 46080              : [64][72] bf16
//   VTH 55296, VTL 64512            : [64][72] bf16 (v transposed: [d][j])
//   BAND 73728 : [128][12] f32, RLS 79872 : [128][9] f32,
//   ERVS 84480 : 576 f32, ERKS 86784 : 576 f32  -> total 89088
#define ATT_SMEM 89088
__global__ __launch_bounds__(256, 2) void attn_fused(
    const float* __restrict__ erv, const float* __restrict__ erk)
{
    extern __shared__ char smc[];
    __nv_bfloat16 (*QH)[72]  = (__nv_bfloat16(*)[72])(smc);
    __nv_bfloat16 (*QL)[72]  = (__nv_bfloat16(*)[72])(smc + 18432);
    __nv_bfloat16 (*KH)[72]  = (__nv_bfloat16(*)[72])(smc + 36864);
    __nv_bfloat16 (*KL)[72]  = (__nv_bfloat16(*)[72])(smc + 46080);
    __nv_bfloat16 (*VTH)[72] = (__nv_bfloat16(*)[72])(smc + 55296);
    __nv_bfloat16 (*VTL)[72] = (__nv_bfloat16(*)[72])(smc + 64512);
    float (*BAND)[12] = (float(*)[12])(smc + 73728);
    float (*RLS)[9]   = (float(*)[9])(smc + 79872);
    float* ERVS       = (float*)(smc + 84480);
    float* ERKS       = (float*)(smc + 86784);

    int tid = threadIdx.x, wid = tid >> 5, lane = tid & 31;
    int g = lane >> 2, tq = lane & 3;
    int bh = blockIdx.y, b = bh >> 4, h = bh & 15;
    int i0 = blockIdx.x * 128;

    // ---- load Q tile (pre-split, direct copies), ERKS/ERVS, zero BAND ----
#pragma unroll
    for (int u = 0; u < 4; ++u) {
        int lin = tid + u * 256;
        int r = lin >> 3, c8 = lin & 7;
        const size_t go = (size_t)(bh * 1024 + i0 + r) * 64 + c8 * 8;
        *(uint4*)&QH[r][c8 * 8] = *(const uint4*)(g_q_hi + go);
        *(uint4*)&QL[r][c8 * 8] = *(const uint4*)(g_q_lo + go);
    }
    for (int idx = tid; idx < 576; idx += 256) { ERVS[idx] = erv[idx]; ERKS[idx] = erk[idx]; }
    for (int idx = tid; idx < 128 * 12; idx += 256) ((float*)BAND)[idx] = 0.f;
    __syncthreads();

    // ---- rel-k logits from resident Q tile ----
    for (int idx = tid; idx < 1152; idx += 256) {
        int r = idx / 9, u = idx - r * 9;
        float s = 0.f;
        const float* e = ERKS + u * 64;
#pragma unroll
        for (int d = 0; d < 64; ++d)
            s += (__bfloat162float(QH[r][d]) + __bfloat162float(QL[r][d])) * e[d];
        RLS[r][u] = s;
    }

    float O[8][4];
#pragma unroll
    for (int nd = 0; nd < 8; ++nd)
#pragma unroll
        for (int e = 0; e < 4; ++e) O[nd][e] = 0.f;
    float m0 = -1e30f, m1 = -1e30f, l0 = 0.f, l1 = 0.f;

    const int rbase = wid * 16 + g;
    // packed mask words for this thread's two rows
    const uint32_t* mrow0 = g_mbits + ((size_t)(b << 10) + i0 + rbase) * 32;
    const uint32_t* mrow1 = mrow0 + 8 * 32;

    for (int jt = 0; jt < 16; ++jt) {
        int j0 = jt * 64;
        __syncthreads();   // protect K/V smem reuse (also covers RLS on jt=0)
        // ---- fill K (direct copies) ----
#pragma unroll
        for (int u = 0; u < 2; ++u) {
            int lin = tid + u * 256;
            int r = lin >> 3, c8 = lin & 7;
            const size_t go = (size_t)(bh * 1024 + j0 + r) * 64 + c8 * 8;
            *(uint4*)&KH[r][c8 * 8] = *(const uint4*)(g_k_hi + go);
            *(uint4*)&KL[r][c8 * 8] = *(const uint4*)(g_k_lo + go);
        }
        // ---- fill V^T (transpose on store) ----
        {
            int jj = tid & 63, qp = tid >> 6;
            const size_t go = (size_t)(bh * 1024 + j0 + jj) * 64 + qp * 16;
#pragma unroll
            for (int u = 0; u < 2; ++u) {
                uint4 vh = *(const uint4*)(g_v_hi + go + u * 8);
                uint4 vl = *(const uint4*)(g_v_lo + go + u * 8);
                const __nv_bfloat16* ph = (const __nv_bfloat16*)&vh;
                const __nv_bfloat16* pl = (const __nv_bfloat16*)&vl;
                int d0 = qp * 16 + u * 8;
#pragma unroll
                for (int i = 0; i < 8; ++i) {
                    VTH[d0 + i][jj] = ph[i];
                    VTL[d0 + i][jj] = pl[i];
                }
            }
        }
        __syncthreads();

        // ---- S = Qs K^T (bf16 split, 3 passes), 64 cols ----
        float S[8][4];
#pragma unroll
        for (int nf = 0; nf < 8; ++nf)
#pragma unroll
            for (int e = 0; e < 4; ++e) S[nf][e] = 0.f;
#pragma unroll
        for (int ks = 0; ks < 4; ++ks) {
            int kof = ks * 16 + 2 * tq;
            uint32_t ah[4], al[4];
            ah[0] = *(const uint32_t*)&QH[rbase][kof];
            ah[1] = *(const uint32_t*)&QH[rbase + 8][kof];
            ah[2] = *(const uint32_t*)&QH[rbase][kof + 8];
            ah[3] = *(const uint32_t*)&QH[rbase + 8][kof + 8];
            al[0] = *(const uint32_t*)&QL[rbase][kof];
            al[1] = *(const uint32_t*)&QL[rbase + 8][kof];
            al[2] = *(const uint32_t*)&QL[rbase][kof + 8];
            al[3] = *(const uint32_t*)&QL[rbase + 8][kof + 8];
#pragma unroll
            for (int nf = 0; nf < 8; ++nf) {
                int col = nf * 8 + g;
                uint32_t bhf[2], blf[2];
                bhf[0] = *(const uint32_t*)&KH[col][kof];
                bhf[1] = *(const uint32_t*)&KH[col][kof + 8];
                blf[0] = *(const uint32_t*)&KL[col][kof];
                blf[1] = *(const uint32_t*)&KL[col][kof + 8];
                mma16816(S[nf], ah, bhf);
                mma16816(S[nf], ah, blf);
                mma16816(S[nf], al, bhf);
            }
        }

        // ---- fixup: rel-k band + mask; row max ----
        uint32_t mw[2][2];
        mw[0][0] = mrow0[(j0 >> 5)];     mw[0][1] = mrow0[(j0 >> 5) + 1];
        mw[1][0] = mrow1[(j0 >> 5)];     mw[1][1] = mrow1[(j0 >> 5) + 1];
        float mx0 = -1e30f, mx1 = -1e30f;
#pragma unroll
        for (int nf = 0; nf < 8; ++nf) {
#pragma unroll
            for (int e = 0; e < 4; ++e) {
                int rl_ = rbase + ((e >> 1) << 3);
                int jloc = nf * 8 + 2 * tq + (e & 1);
                float s = S[nf][e];
                int d = (j0 + jloc) - (i0 + rl_);
                if ((unsigned)(d + 4) <= 8u) s += RLS[rl_][d + 4];
                if (((mw[e >> 1][nf >> 2] >> (jloc & 31)) & 1u) == 0u) s = 1e-4f;
                S[nf][e] = s;
                if (e < 2) mx0 = fmaxf(mx0, s); else mx1 = fmaxf(mx1, s);
            }
        }
        mx0 = fmaxf(mx0, __shfl_xor_sync(0xffffffffu, mx0, 1));
        mx0 = fmaxf(mx0, __shfl_xor_sync(0xffffffffu, mx0, 2));
        mx1 = fmaxf(mx1, __shfl_xor_sync(0xffffffffu, mx1, 1));
        mx1 = fmaxf(mx1, __shfl_xor_sync(0xffffffffu, mx1, 2));
        float mn0 = fmaxf(m0, mx0), mn1 = fmaxf(m1, mx1);
        float a0 = __expf(m0 - mn0), a1 = __expf(m1 - mn1);
        m0 = mn0; m1 = mn1;

#pragma unroll
        for (int nd = 0; nd < 8; ++nd) {
            O[nd][0] *= a0; O[nd][1] *= a0; O[nd][2] *= a1; O[nd][3] *= a1;
        }
        if (tq == 0) {
#pragma unroll
            for (int u = 0; u < 9; ++u) {
                BAND[rbase][u] *= a0;
                BAND[rbase + 8][u] *= a1;
            }
        }
        __syncwarp();

        // ---- p = exp(s - m), row sums, band adds ----
        float s0 = 0.f, s1 = 0.f;
#pragma unroll
        for (int nf = 0; nf < 8; ++nf) {
#pragma unroll
            for (int e = 0; e < 4; ++e) {
                float p = __expf(S[nf][e] - ((e < 2) ? mn0 : mn1));
                S[nf][e] = p;
                if (e < 2) s0 += p; else s1 += p;
                int rl_ = rbase + ((e >> 1) << 3);
                int d = (j0 + nf * 8 + 2 * tq + (e & 1)) - (i0 + rl_);
                if ((unsigned)(d + 4) <= 8u) BAND[rl_][d + 4] += p;
            }
        }
        s0 += __shfl_xor_sync(0xffffffffu, s0, 1);
        s0 += __shfl_xor_sync(0xffffffffu, s0, 2);
        s1 += __shfl_xor_sync(0xffffffffu, s1, 1);
        s1 += __shfl_xor_sync(0xffffffffu, s1, 2);
        l0 = l0 * a0 + s0;
        l1 = l1 * a1 + s1;

        // ---- O += P V (split P in-register; 3 passes) ----
#pragma unroll
        for (int kj = 0; kj < 4; ++kj) {
            uint32_t aH[4], aL[4];
            split_pack(S[2 * kj][0],     S[2 * kj][1],     aH[0], aL[0]);
            split_pack(S[2 * kj][2],     S[2 * kj][3],     aH[1], aL[1]);
            split_pack(S[2 * kj + 1][0], S[2 * kj + 1][1], aH[2], aL[2]);
            split_pack(S[2 * kj + 1][2], S[2 * kj + 1][3], aH[3], aL[3]);
            int kof = kj * 16 + 2 * tq;
#pragma unroll
            for (int nd = 0; nd < 8; ++nd) {
                int col = nd * 8 + g;
                uint32_t bHf[2], bLf[2];
                bHf[0] = *(const uint32_t*)&VTH[col][kof];
                bHf[1] = *(const uint32_t*)&VTH[col][kof + 8];
                bLf[0] = *(const uint32_t*)&VTL[col][kof];
                bLf[1] = *(const uint32_t*)&VTL[col][kof + 8];
                mma16816(O[nd], aH, bHf);
                mma16816(O[nd], aH, bLf);
                mma16816(O[nd], aL, bHf);
            }
        }
    }
    __syncwarp();

    // ---- epilogue: out = (O + band . erv) / l, write bf16-split g_att ----
    float inv0 = 1.f / l0, inv1 = 1.f / l1;
#pragma unroll
    for (int e = 0; e < 4; ++e) {
        int rl_ = rbase + ((e >> 1) << 3);
        float bnd[9];
#pragma unroll
        for (int u = 0; u < 9; ++u) bnd[u] = BAND[rl_][u];
        float inv = (e < 2) ? inv0 : inv1;
        size_t rowbase = ((size_t)(b * 1024 + i0 + rl_)) * 1024 + h * 64;
#pragma unroll
        for (int nd = 0; nd < 8; ++nd) {
            int dcol = nd * 8 + 2 * tq + (e & 1);
            float val = O[nd][e];
#pragma unroll
            for (int u = 0; u < 9; ++u) val += bnd[u] * ERVS[u * 64 + dcol];
            val *= inv;
            __nv_bfloat16 hh, ll;
            splitbf(val, hh, ll);
            g_att_hi[rowbase + dcol] = hh;
            g_att_lo[rowbase + dcol] = ll;
        }
    }
}

// --------------------------------- launch --------------------------------------
extern "C" void kernel_launch(void* const* d_in, const int* in_sizes, int n_in,
                              void* d_out, int out_size)
{
    const float* x   = (const float*)d_in[0];
    const float* c   = (const float*)d_in[1];
    const int*   msk = (const int*)  d_in[2];
    const float* Wq  = (const float*)d_in[3];
    const float* bq  = (const float*)d_in[4];
    const float* Wk  = (const float*)d_in[5];
    const float* bk  = (const float*)d_in[6];
    const float* Wv  = (const float*)d_in[7];
    const float* bv  = (const float*)d_in[8];
    const float* Wo  = (const float*)d_in[9];
    const float* bo  = (const float*)d_in[10];
    const float* erk = (const float*)d_in[11];
    const float* erv = (const float*)d_in[12];
    float* out = (float*)d_out;

    cudaFuncSetAttribute(gemm_mma, cudaFuncAttributeMaxDynamicSharedMemorySize, GEMM_SMEM);
    cudaFuncSetAttribute(attn_fused, cudaFuncAttributeMaxDynamicSharedMemorySize, ATT_SMEM);

    conv_in<<<4096, 256>>>(x, c, bq, bk, bv, bo);
    conv_w<<<dim3(32, 32, 4), 256>>>(Wq, Wk, Wv, Wo);
    mask_pack<<<8192, 256>>>(msk);
    gemm_mma<<<dim3(8, 16, 3), 256, GEMM_SMEM>>>(0, nullptr);   // Q,K,V
    attn_fused<<<dim3(8, 32), 256, ATT_SMEM>>>(erv, erk);       // 8 i-tiles x 32 bh
    gemm_mma<<<dim3(8, 16, 1), 256, GEMM_SMEM>>>(1, out);       // @Wo + bo
}

// round 8
// speedup vs baseline: 2.6748x; 1.0508x over previous
#include <cuda_runtime.h>
#include <cuda_bf16.h>
#include <cstdint>

// Problem constants
#define B_   2
#define T_   1024
#define CH_  1024
#define H_   16
#define KC_  64
#define WIN_ 4
#define MROWS (B_ * T_)          // 2048
#define BHT  (B_ * H_ * T_)      // 32768

// ---------------- scratch (static device globals; no allocation) ----------------
__device__ __nv_bfloat16 g_q_hi[BHT * KC_];
__device__ __nv_bfloat16 g_q_lo[BHT * KC_];
__device__ __nv_bfloat16 g_k_hi[BHT * KC_];
__device__ __nv_bfloat16 g_k_lo[BHT * KC_];
__device__ __nv_bfloat16 g_v_hi[BHT * KC_];
__device__ __nv_bfloat16 g_v_lo[BHT * KC_];

__device__ __nv_bfloat16 gx_hi[MROWS * CH_];
__device__ __nv_bfloat16 gx_lo[MROWS * CH_];
__device__ __nv_bfloat16 gc_hi[MROWS * CH_];
__device__ __nv_bfloat16 gc_lo[MROWS * CH_];
__device__ __nv_bfloat16 gw_hi[4 * CH_ * CH_];   // W^T concat [q|k|v|o]
__device__ __nv_bfloat16 gw_lo[4 * CH_ * CH_];
__device__ __nv_bfloat16 g_att_hi[MROWS * CH_];
__device__ __nv_bfloat16 g_att_lo[MROWS * CH_];
__device__ float g_bias[4 * CH_];
__device__ uint32_t g_mbits[MROWS * (T_ / 32)];

// ======================= helpers ================================================
__device__ __forceinline__ void mma16816(float* c, const uint32_t* a, const uint32_t* b)
{
    asm volatile(
        "mma.sync.aligned.m16n8k16.row.col.f32.bf16.bf16.f32 "
        "{%0,%1,%2,%3}, {%4,%5,%6,%7}, {%8,%9}, {%0,%1,%2,%3};"
        : "+f"(c[0]), "+f"(c[1]), "+f"(c[2]), "+f"(c[3])
        : "r"(a[0]), "r"(a[1]), "r"(a[2]), "r"(a[3]), "r"(b[0]), "r"(b[1]));
}

__device__ __forceinline__ void ldm_x4(uint32_t* r, uint32_t addr)
{
    asm volatile(
        "ldmatrix.sync.aligned.m8n8.x4.shared.b16 {%0,%1,%2,%3}, [%4];"
        : "=r"(r[0]), "=r"(r[1]), "=r"(r[2]), "=r"(r[3]) : "r"(addr));
}

__device__ __forceinline__ void splitbf(float x, __nv_bfloat16& h, __nv_bfloat16& l)
{
    h = __float2bfloat16_rn(x);
    l = __float2bfloat16_rn(x - __bfloat162float(h));
}

__device__ __forceinline__ void split_pack(float x, float y, uint32_t& hi, uint32_t& lo)
{
    __nv_bfloat16 hx, lx, hy, ly;
    splitbf(x, hx, lx); splitbf(y, hy, ly);
    __nv_bfloat162 th = __halves2bfloat162(hx, hy);
    __nv_bfloat162 tl = __halves2bfloat162(lx, ly);
    hi = *reinterpret_cast<uint32_t*>(&th);
    lo = *reinterpret_cast<uint32_t*>(&tl);
}

__device__ __forceinline__ uint32_t smem_u32(const void* p) {
    uint32_t a;
    asm("{ .reg .u64 t; cvta.to.shared.u64 t, %1; cvt.u32.u64 %0, t; }"
        : "=r"(a) : "l"(p));
    return a;
}

__device__ __forceinline__ void cpa16(uint32_t dst, const void* src) {
    asm volatile("cp.async.cg.shared.global [%0], [%1], 16;" :: "r"(dst), "l"(src));
}

// ======================= prep kernels ==========================================
__global__ __launch_bounds__(256) void conv_in(
    const float* __restrict__ x, const float* __restrict__ c,
    const float* __restrict__ bq, const float* __restrict__ bk,
    const float* __restrict__ bv, const float* __restrict__ bo)
{
    int i = blockIdx.x * 256 + threadIdx.x;
    const float4* src;
    __nv_bfloat162 *dh, *dl;
    int j;
    if (i < 524288) {
        src = (const float4*)x; j = i;
        dh = (__nv_bfloat162*)gx_hi; dl = (__nv_bfloat162*)gx_lo;
    } else {
        src = (const float4*)c; j = i - 524288;
        dh = (__nv_bfloat162*)gc_hi; dl = (__nv_bfloat162*)gc_lo;
    }
    float4 v = src[j];
    __nv_bfloat16 hx, lx, hy, ly, hz, lz, hw, lw;
    splitbf(v.x, hx, lx); splitbf(v.y, hy, ly);
    splitbf(v.z, hz, lz); splitbf(v.w, hw, lw);
    dh[2 * j]     = __halves2bfloat162(hx, hy);
    dh[2 * j + 1] = __halves2bfloat162(hz, hw);
    dl[2 * j]     = __halves2bfloat162(lx, ly);
    dl[2 * j + 1] = __halves2bfloat162(lz, lw);
    if (i < 4096) {
        float b = (i < 1024) ? bq[i] : (i < 2048) ? bk[i - 1024]
                : (i < 3072) ? bv[i - 2048] : bo[i - 3072];
        g_bias[i] = b;
    }
}

__global__ __launch_bounds__(256) void conv_w(
    const float* __restrict__ Wq, const float* __restrict__ Wk,
    const float* __restrict__ Wv, const float* __restrict__ Wo)
{
    __shared__ float tile[32][33];
    int z = blockIdx.z;
    const float* W = (z == 0) ? Wq : (z == 1) ? Wk : (z == 2) ? Wv : Wo;
    int n0 = blockIdx.x * 32, k0 = blockIdx.y * 32;
    int tx = threadIdx.x & 31, ty = threadIdx.x >> 5;
#pragma unroll
    for (int u = 0; u < 4; ++u) {
        int k = k0 + ty + u * 8;
        tile[ty + u * 8][tx] = W[k * 1024 + n0 + tx];
    }
    __syncthreads();
#pragma unroll
    for (int u = 0; u < 4; ++u) {
        int r = ty + u * 8;
        float v = tile[tx][r];
        int dst = (z * 1024 + n0 + r) * 1024 + k0 + tx;
        __nv_bfloat16 h, l;
        splitbf(v, h, l);
        gw_hi[dst] = h;
        gw_lo[dst] = l;
    }
}

__global__ __launch_bounds__(256) void mask_pack(const int* __restrict__ mask)
{
    int idx = blockIdx.x * 256 + threadIdx.x;
    uint32_t bits = __ballot_sync(0xffffffffu, mask[idx] != 0);
    if ((threadIdx.x & 31) == 0) g_mbits[idx >> 5] = bits;
}

// ======================= cp.async double-buffered bf16-split GEMM ==============
#define LDK 72                        // padded k-stride (bf16), 144B rows
#define TILE_B (128 * LDK * 2)        // 18432 B
#define STAGE_B (4 * TILE_B)          // 73728 B
#define GEMM_SMEM (2 * STAGE_B)       // 147456 B
__global__ __launch_bounds__(256) void gemm_mma(int mode, float* __restrict__ finalout)
{
    extern __shared__ __nv_bfloat16 sm[];
    uint32_t sbase = smem_u32(sm);

    int tid = threadIdx.x;
    int wid = tid >> 5, lane = tid & 31;
    int g = lane >> 2, tg = lane & 3;
    int warp_m = wid & 1, warp_n = wid >> 1;
    int z = (mode == 0) ? (int)blockIdx.z : 3;

    const __nv_bfloat16 *A_hi, *A_lo;
    if (mode == 0) {
        if (z == 0) { A_hi = gx_hi; A_lo = gx_lo; }
        else        { A_hi = gc_hi; A_lo = gc_lo; }
    } else { A_hi = g_att_hi; A_lo = g_att_lo; }
    int arow0 = blockIdx.y * 128;
    int brow0 = z * 1024 + blockIdx.x * 128;

    auto issue_stage = [&](int stage, int k0) {
        const __nv_bfloat16* srcs[4] = {A_hi, A_lo, gw_hi, gw_lo};
        int rows0[4] = {arow0, arow0, brow0, brow0};
        uint32_t stoff = sbase + (uint32_t)stage * STAGE_B;
#pragma unroll
        for (int arr = 0; arr < 4; ++arr) {
#pragma unroll
            for (int u = 0; u < 4; ++u) {
                int lin = tid + u * 256;
                int r = lin >> 3, c8 = lin & 7;
                cpa16(stoff + (uint32_t)arr * TILE_B + r * 144 + c8 * 16,
                      srcs[arr] + (size_t)(rows0[arr] + r) * 1024 + k0 + c8 * 8);
            }
        }
        asm volatile("cp.async.commit_group;" ::: "memory");
    };

    float acc[4][4][4];
#pragma unroll
    for (int mi = 0; mi < 4; ++mi)
#pragma unroll
        for (int ni = 0; ni < 4; ++ni)
#pragma unroll
            for (int e = 0; e < 4; ++e) acc[mi][ni][e] = 0.f;

    // ldmatrix per-thread offsets
    uint32_t a_off = (uint32_t)((warp_m * 64 + (lane & 15)) * 144 + ((lane >> 4) << 4));
    uint32_t b_off = (uint32_t)((warp_n * 32 + (((lane >> 4) & 1) << 3) + (lane & 7)) * 144
                                + (((lane >> 3) & 1) << 4));

    issue_stage(0, 0);

    for (int s = 0; s < 16; ++s) {
        asm volatile("cp.async.wait_group 0;" ::: "memory");
        __syncthreads();
        if (s + 1 < 16) issue_stage((s + 1) & 1, (s + 1) * 64);

        uint32_t stb = sbase + (uint32_t)(s & 1) * STAGE_B;
        uint32_t aHb = stb, aLb = stb + TILE_B, bHb = stb + 2 * TILE_B, bLb = stb + 3 * TILE_B;

#pragma unroll
        for (int kk = 0; kk < 4; ++kk) {
            uint32_t kb = (uint32_t)kk * 32;
            uint32_t ah[4][4], al[4][4], bh[2][4], bl[2][4];
#pragma unroll
            for (int mi = 0; mi < 4; ++mi) {
                ldm_x4(ah[mi], aHb + a_off + (uint32_t)mi * (16 * 144) + kb);
                ldm_x4(al[mi], aLb + a_off + (uint32_t)mi * (16 * 144) + kb);
            }
#pragma unroll
            for (int p = 0; p < 2; ++p) {
                ldm_x4(bh[p], bHb + b_off + (uint32_t)p * (16 * 144) + kb);
                ldm_x4(bl[p], bLb + b_off + (uint32_t)p * (16 * 144) + kb);
            }
#pragma unroll
            for (int mi = 0; mi < 4; ++mi)
#pragma unroll
                for (int ni = 0; ni < 4; ++ni) {
                    const uint32_t* bhf = &bh[ni >> 1][(ni & 1) * 2];
                    const uint32_t* blf = &bl[ni >> 1][(ni & 1) * 2];
                    mma16816(acc[mi][ni], ah[mi], bhf);
                    mma16816(acc[mi][ni], ah[mi], blf);
                    mma16816(acc[mi][ni], al[mi], bhf);
                }
        }
        // NOTE: no end-of-stage sync needed — the top-of-loop wait+sync of the
        // next iteration orders buffer reuse (issue for s+2 happens after it).
    }

    float scale = (mode == 0 && z == 0) ? 0.125f : 1.0f;
    __nv_bfloat16* dsth = (z == 0) ? g_q_hi : (z == 1) ? g_k_hi : g_v_hi;
    __nv_bfloat16* dstl = (z == 0) ? g_q_lo : (z == 1) ? g_k_lo : g_v_lo;
#pragma unroll
    for (int mi = 0; mi < 4; ++mi) {
#pragma unroll
        for (int ni = 0; ni < 4; ++ni) {
#pragma unroll
            for (int e = 0; e < 4; ++e) {
                int row = blockIdx.y * 128 + warp_m * 64 + mi * 16 + g + ((e >> 1) ? 8 : 0);
                int col = blockIdx.x * 128 + warp_n * 32 + ni * 8 + 2 * tg + (e & 1);
                float v = (acc[mi][ni][e] + g_bias[z * 1024 + col]) * scale;
                if (mode == 0) {
                    int h = col >> 6, bb = row >> 10, t = row & 1023, d = col & 63;
                    int idx = (((bb * 16 + h) << 16) | (t << 6)) + d;
                    __nv_bfloat16 hh, ll;
                    splitbf(v, hh, ll);
                    dsth[idx] = hh;
                    dstl[idx] = ll;
                } else {
                    finalout[(size_t)row * 1024 + col] = v;
                }
            }
        }
    }
}

// =================== fused flash attention ======================================
// grid (8, 32), 256 threads, 2 CTAs/SM. i-tile=128, j-tile=64.
#define ATT_SMEM 89088
__global__ __launch_bounds__(256, 2) void attn_fused(
    const float* __restrict__ erv, const float* __restrict__ erk)
{
    extern __shared__ char smc[];
    __nv_bfloat16 (*QH)[72]  = (__nv_bfloat16(*)[72])(smc);
    __nv_bfloat16 (*QL)[72]  = (__nv_bfloat16(*)[72])(smc + 18432);
    __nv_bfloat16 (*KH)[72]  = (__nv_bfloat16(*)[72])(smc + 36864);
    __nv_bfloat16 (*KL)[72]  = (__nv_bfloat16(*)[72])(smc + 46080);
    __nv_bfloat16 (*VTH)[72] = (__nv_bfloat16(*)[72])(smc + 55296);
    __nv_bfloat16 (*VTL)[72] = (__nv_bfloat16(*)[72])(smc + 64512);
    float (*BAND)[12] = (float(*)[12])(smc + 73728);
    float (*RLS)[9]   = (float(*)[9])(smc + 79872);
    float* ERVS       = (float*)(smc + 84480);
    float* ERKS       = (float*)(smc + 86784);

    uint32_t sb = smem_u32(smc);
    const uint32_t QH_a = sb, QL_a = sb + 18432, KH_a = sb + 36864, KL_a = sb + 46080;
    const uint32_t VTH_a = sb + 55296, VTL_a = sb + 64512;

    int tid = threadIdx.x, wid = tid >> 5, lane = tid & 31;
    int g = lane >> 2, tq = lane & 3;
    int bh = blockIdx.y, b = bh >> 4, h = bh & 15;
    int i0 = blockIdx.x * 128;

    // ldmatrix per-thread offsets
    uint32_t q_off = (uint32_t)((wid * 16 + (lane & 15)) * 144 + ((lane >> 4) << 4));
    uint32_t k_off = (uint32_t)(((((lane >> 4) & 1) << 3) + (lane & 7)) * 144
                                + (((lane >> 3) & 1) << 4));

    // ---- load Q tile (pre-split), ERKS/ERVS, zero BAND ----
#pragma unroll
    for (int u = 0; u < 4; ++u) {
        int lin = tid + u * 256;
        int r = lin >> 3, c8 = lin & 7;
        const size_t go = (size_t)(bh * 1024 + i0 + r) * 64 + c8 * 8;
        *(uint4*)&QH[r][c8 * 8] = *(const uint4*)(g_q_hi + go);
        *(uint4*)&QL[r][c8 * 8] = *(const uint4*)(g_q_lo + go);
    }
    for (int idx = tid; idx < 576; idx += 256) { ERVS[idx] = erv[idx]; ERKS[idx] = erk[idx]; }
    for (int idx = tid; idx < 128 * 12; idx += 256) ((float*)BAND)[idx] = 0.f;
    __syncthreads();

    // ---- rel-k logits from resident Q tile ----
    for (int idx = tid; idx < 1152; idx += 256) {
        int r = idx / 9, u = idx - r * 9;
        float s = 0.f;
        const float* e = ERKS + u * 64;
#pragma unroll
        for (int d = 0; d < 64; ++d)
            s += (__bfloat162float(QH[r][d]) + __bfloat162float(QL[r][d])) * e[d];
        RLS[r][u] = s;
    }

    float O[8][4];
#pragma unroll
    for (int nd = 0; nd < 8; ++nd)
#pragma unroll
        for (int e = 0; e < 4; ++e) O[nd][e] = 0.f;
    float m0 = -1e30f, m1 = -1e30f, l0 = 0.f, l1 = 0.f;

    const int rbase = wid * 16 + g;
    const uint32_t* mrow0 = g_mbits + ((size_t)(b << 10) + i0 + rbase) * 32;
    const uint32_t* mrow1 = mrow0 + 8 * 32;

    for (int jt = 0; jt < 16; ++jt) {
        int j0 = jt * 64;
        __syncthreads();
        // ---- fill K ----
#pragma unroll
        for (int u = 0; u < 2; ++u) {
            int lin = tid + u * 256;
            int r = lin >> 3, c8 = lin & 7;
            const size_t go = (size_t)(bh * 1024 + j0 + r) * 64 + c8 * 8;
            *(uint4*)&KH[r][c8 * 8] = *(const uint4*)(g_k_hi + go);
            *(uint4*)&KL[r][c8 * 8] = *(const uint4*)(g_k_lo + go);
        }
        // ---- fill V^T ----
        {
            int jj = tid & 63, qp = tid >> 6;
            const size_t go = (size_t)(bh * 1024 + j0 + jj) * 64 + qp * 16;
#pragma unroll
            for (int u = 0; u < 2; ++u) {
                uint4 vh = *(const uint4*)(g_v_hi + go + u * 8);
                uint4 vl = *(const uint4*)(g_v_lo + go + u * 8);
                const __nv_bfloat16* ph = (const __nv_bfloat16*)&vh;
                const __nv_bfloat16* pl = (const __nv_bfloat16*)&vl;
                int d0 = qp * 16 + u * 8;
#pragma unroll
                for (int i = 0; i < 8; ++i) {
                    VTH[d0 + i][jj] = ph[i];
                    VTL[d0 + i][jj] = pl[i];
                }
            }
        }
        __syncthreads();

        // ---- S = Qs K^T (bf16 split, 3 passes), ldmatrix frags ----
        float S[8][4];
#pragma unroll
        for (int nf = 0; nf < 8; ++nf)
#pragma unroll
            for (int e = 0; e < 4; ++e) S[nf][e] = 0.f;
#pragma unroll
        for (int ks = 0; ks < 4; ++ks) {
            uint32_t kb = (uint32_t)ks * 32;
            uint32_t ah[4], al[4];
            ldm_x4(ah, QH_a + q_off + kb);
            ldm_x4(al, QL_a + q_off + kb);
#pragma unroll
            for (int p = 0; p < 4; ++p) {
                uint32_t bh4[4], bl4[4];
                ldm_x4(bh4, KH_a + k_off + (uint32_t)p * (16 * 144) + kb);
                ldm_x4(bl4, KL_a + k_off + (uint32_t)p * (16 * 144) + kb);
                mma16816(S[2 * p],     ah, bh4);
                mma16816(S[2 * p],     ah, bl4);
                mma16816(S[2 * p],     al, bh4);
                mma16816(S[2 * p + 1], ah, bh4 + 2);
                mma16816(S[2 * p + 1], ah, bl4 + 2);
                mma16816(S[2 * p + 1], al, bh4 + 2);
            }
        }

        // ---- fixup: rel-k band + mask; row max ----
        uint32_t mw[2][2];
        mw[0][0] = mrow0[(j0 >> 5)];     mw[0][1] = mrow0[(j0 >> 5) + 1];
        mw[1][0] = mrow1[(j0 >> 5)];     mw[1][1] = mrow1[(j0 >> 5) + 1];
        float mx0 = -1e30f, mx1 = -1e30f;
#pragma unroll
        for (int nf = 0; nf < 8; ++nf) {
#pragma unroll
            for (int e = 0; e < 4; ++e) {
                int rl_ = rbase + ((e >> 1) << 3);
                int jloc = nf * 8 + 2 * tq + (e & 1);
                float s = S[nf][e];
                int d = (j0 + jloc) - (i0 + rl_);
                if ((unsigned)(d + 4) <= 8u) s += RLS[rl_][d + 4];
                if (((mw[e >> 1][nf >> 2] >> (jloc & 31)) & 1u) == 0u) s = 1e-4f;
                S[nf][e] = s;
                if (e < 2) mx0 = fmaxf(mx0, s); else mx1 = fmaxf(mx1, s);
            }
        }
        mx0 = fmaxf(mx0, __shfl_xor_sync(0xffffffffu, mx0, 1));
        mx0 = fmaxf(mx0, __shfl_xor_sync(0xffffffffu, mx0, 2));
        mx1 = fmaxf(mx1, __shfl_xor_sync(0xffffffffu, mx1, 1));
        mx1 = fmaxf(mx1, __shfl_xor_sync(0xffffffffu, mx1, 2));
        float mn0 = fmaxf(m0, mx0), mn1 = fmaxf(m1, mx1);
        float a0 = __expf(m0 - mn0), a1 = __expf(m1 - mn1);
        m0 = mn0; m1 = mn1;

#pragma unroll
        for (int nd = 0; nd < 8; ++nd) {
            O[nd][0] *= a0; O[nd][1] *= a0; O[nd][2] *= a1; O[nd][3] *= a1;
        }
        if (tq == 0) {
#pragma unroll
            for (int u = 0; u < 9; ++u) {
                BAND[rbase][u] *= a0;
                BAND[rbase + 8][u] *= a1;
            }
        }
        __syncwarp();

        // ---- p = exp(s - m), row sums, band adds ----
        float s0 = 0.f, s1 = 0.f;
#pragma unroll
        for (int nf = 0; nf < 8; ++nf) {
#pragma unroll
            for (int e = 0; e < 4; ++e) {
                float p = __expf(S[nf][e] - ((e < 2) ? mn0 : mn1));
                S[nf][e] = p;
                if (e < 2) s0 += p; else s1 += p;
                int rl_ = rbase + ((e >> 1) << 3);
                int d = (j0 + nf * 8 + 2 * tq + (e & 1)) - (i0 + rl_);
                if ((unsigned)(d + 4) <= 8u) BAND[rl_][d + 4] += p;
            }
        }
        s0 += __shfl_xor_sync(0xffffffffu, s0, 1);
        s0 += __shfl_xor_sync(0xffffffffu, s0, 2);
        s1 += __shfl_xor_sync(0xffffffffu, s1, 1);
        s1 += __shfl_xor_sync(0xffffffffu, s1, 2);
        l0 = l0 * a0 + s0;
        l1 = l1 * a1 + s1;

        // ---- O += P V (split P in-register; ldmatrix V frags; 3 passes) ----
#pragma unroll
        for (int kj = 0; kj < 4; ++kj) {
            uint32_t aH[4], aL[4];
            split_pack(S[2 * kj][0],     S[2 * kj][1],     aH[0], aL[0]);
            split_pack(S[2 * kj][2],     S[2 * kj][3],     aH[1], aL[1]);
            split_pack(S[2 * kj + 1][0], S[2 * kj + 1][1], aH[2], aL[2]);
            split_pack(S[2 * kj + 1][2], S[2 * kj + 1][3], aH[3], aL[3]);
            uint32_t kb = (uint32_t)kj * 32;
#pragma unroll
            for (int p = 0; p < 4; ++p) {
                uint32_t vh4[4], vl4[4];
                ldm_x4(vh4, VTH_a + k_off + (uint32_t)p * (16 * 144) + kb);
                ldm_x4(vl4, VTL_a + k_off + (uint32_t)p * (16 * 144) + kb);
                mma16816(O[2 * p],     aH, vh4);
                mma16816(O[2 * p],     aH, vl4);
                mma16816(O[2 * p],     aL, vh4);
                mma16816(O[2 * p + 1], aH, vh4 + 2);
                mma16816(O[2 * p + 1], aH, vl4 + 2);
                mma16816(O[2 * p + 1], aL, vh4 + 2);
            }
        }
    }
    __syncwarp();

    // ---- epilogue ----
    float inv0 = 1.f / l0, inv1 = 1.f / l1;
#pragma unroll
    for (int e = 0; e < 4; ++e) {
        int rl_ = rbase + ((e >> 1) << 3);
        float bnd[9];
#pragma unroll
        for (int u = 0; u < 9; ++u) bnd[u] = BAND[rl_][u];
        float inv = (e < 2) ? inv0 : inv1;
        size_t rowbase = ((size_t)(b * 1024 + i0 + rl_)) * 1024 + h * 64;
#pragma unroll
        for (int nd = 0; nd < 8; ++nd) {
            int dcol = nd * 8 + 2 * tq + (e & 1);
            float val = O[nd][e];
#pragma unroll
            for (int u = 0; u < 9; ++u) val += bnd[u] * ERVS[u * 64 + dcol];
            val *= inv;
            __nv_bfloat16 hh, ll;
            splitbf(val, hh, ll);
            g_att_hi[rowbase + dcol] = hh;
            g_att_lo[rowbase + dcol] = ll;
        }
    }
}

// --------------------------------- launch --------------------------------------
extern "C" void kernel_launch(void* const* d_in, const int* in_sizes, int n_in,
                              void* d_out, int out_size)
{
    const float* x   = (const float*)d_in[0];
    const float* c   = (const float*)d_in[1];
    const int*   msk = (const int*)  d_in[2];
    const float* Wq  = (const float*)d_in[3];
    const float* bq  = (const float*)d_in[4];
    const float* Wk  = (const float*)d_in[5];
    const float* bk  = (const float*)d_in[6];
    const float* Wv  = (const float*)d_in[7];
    const float* bv  = (const float*)d_in[8];
    const float* Wo  = (const float*)d_in[9];
    const float* bo  = (const float*)d_in[10];
    const float* erk = (const float*)d_in[11];
    const float* erv = (const float*)d_in[12];
    float* out = (float*)d_out;

    cudaFuncSetAttribute(gemm_mma, cudaFuncAttributeMaxDynamicSharedMemorySize, GEMM_SMEM);
    cudaFuncSetAttribute(attn_fused, cudaFuncAttributeMaxDynamicSharedMemorySize, ATT_SMEM);

    conv_in<<<4096, 256>>>(x, c, bq, bk, bv, bo);
    conv_w<<<dim3(32, 32, 4), 256>>>(Wq, Wk, Wv, Wo);
    mask_pack<<<8192, 256>>>(msk);
    gemm_mma<<<dim3(8, 16, 3), 256, GEMM_SMEM>>>(0, nullptr);   // Q,K,V
    attn_fused<<<dim3(8, 32), 256, ATT_SMEM>>>(erv, erk);
    gemm_mma<<<dim3(8, 16, 1), 256, GEMM_SMEM>>>(1, out);       // @Wo + bo
}